// round 5
// baseline (speedup 1.0000x reference)
#include <cuda_runtime.h>

#define THREADS 256
#define BT      28      // batches per CTA
#define NB      7       // batches per thread (and per warp-pair)
#define HD      64      // hidden
#define GD      256     // 4*H
#define TT      168
#define ID      4
#define BATCH   4096
#define WP      68      // padded row stride: stride%32==4 -> conflict-free LDS.128
#define NGRID   147     // ceil(4096/28)

typedef unsigned long long u64;

__device__ __forceinline__ void ffma2(u64 &d, u64 a, u64 b) {
    asm("fma.rn.f32x2 %0, %1, %2, %0;" : "+l"(d) : "l"(a), "l"(b));
}
__device__ __forceinline__ float red2(u64 v) {
    return __uint_as_float((unsigned)v) + __uint_as_float((unsigned)(v >> 32));
}
__device__ __forceinline__ u64 pack2(float lo, float hi) {
    return (u64)__float_as_uint(lo) | ((u64)__float_as_uint(hi) << 32);
}
__device__ __forceinline__ float tanhapx(float x) {
    float y; asm("tanh.approx.f32 %0, %1;" : "=f"(y) : "f"(x)); return y;
}
__device__ __forceinline__ float fsig(float x) {       // 1 MUFU + fma
    return fmaf(0.5f, tanhapx(0.5f * x), 0.5f);
}
// 64-thread named barrier: warp-pair scoped sync (ids 1..4)
__device__ __forceinline__ void pairbar(int id) {
    asm volatile("bar.sync %0, 64;" :: "r"(id) : "memory");
}

extern "C" __global__ void __launch_bounds__(THREADS, 1)
weather_lstm_kernel(const float* __restrict__ x,
                    const float* __restrict__ Wih0, const float* __restrict__ Whh0,
                    const float* __restrict__ bih0, const float* __restrict__ bhh0,
                    const float* __restrict__ Wih1, const float* __restrict__ Whh1,
                    const float* __restrict__ bih1, const float* __restrict__ bhh1,
                    const float* __restrict__ W1,  const float* __restrict__ b1,
                    const float* __restrict__ W2,  const float* __restrict__ b2,
                    float* __restrict__ out)
{
    extern __shared__ float sm[];
    float* sW0  = sm;                       // Whh0 [256][68]
    float* sW1i = sW0  + GD * WP;           // Wih1 [256][68]
    float* sW1h = sW1i + GD * WP;           // Whh1 [256][68]
    float* sH0  = sW1h + GD * WP;           // h layer0 [28][68]   (pair-private rows)
    float* sH1  = sH0  + BT * WP;           // h layer1 [28][68]   (pair-private rows)
    float* sX   = sH1  + BT * WP;           // x_t [28][4]         (pair-private rows)

    const int t     = threadIdx.x;
    const int u     = t & 63;               // hidden unit owned by this thread
    const int pid   = t >> 6;               // warp-pair id (0..3)
    const int b0    = pid * NB;             // first batch of this pair
    const int barid = pid + 1;              // named barrier id
    const int bBase = blockIdx.x * BT;

    // ---- preload weights into SMEM ----
    for (int e = t; e < GD * HD; e += THREADS) {
        int j = e >> 6, k = e & 63;
        sW0 [j * WP + k] = Whh0[e];
        sW1i[j * WP + k] = Wih1[e];
        sW1h[j * WP + k] = Whh1[e];
    }
    for (int e = t; e < BT * WP; e += THREADS) { sH0[e] = 0.f; sH1[e] = 0.f; }
    // pair-private x load: first 28 threads of each pair load its 7 batches x 4 inputs
    const int lx   = u;                      // 0..63 within pair
    const int bpre = b0 + (lx >> 2);         // local batch for x duty
    const int ipre = lx & 3;
    const bool xok = (lx < 4 * NB) && (bBase + bpre < BATCH);
    if (xok)
        sX[bpre * ID + ipre] = x[(size_t)(bBase + bpre) * (TT * ID) + ipre];
    else if (lx < 4 * NB)
        sX[bpre * ID + ipre] = 0.f;

    // ---- per-thread constants ----
    float bias0[4], bias1[4], w0x[4][4];
    #pragma unroll
    for (int g = 0; g < 4; g++) {
        int j = u + 64 * g;
        bias0[g] = bih0[j] + bhh0[j];
        bias1[g] = bih1[j] + bhh1[j];
        #pragma unroll
        for (int i = 0; i < ID; i++) w0x[g][i] = Wih0[j * ID + i];
    }
    float c0[NB], c1[NB];
    #pragma unroll
    for (int b = 0; b < NB; b++) { c0[b] = 0.f; c1[b] = 0.f; }

    __syncthreads();     // weights + initial state visible to all

    for (int step = 0; step < TT; step++) {
        // prefetch x for step+1 (hidden behind phase-1 matvecs)
        float xpre = 0.f;
        if (xok && step + 1 < TT)
            xpre = x[(size_t)(bBase + bpre) * (TT * ID) + (step + 1) * ID + ipre];

        // ======== phase 1a : layer0  acc0 = bias + Wih0*x + Whh0*h0_{t-1} ====
        u64 acc0[4][NB];
        #pragma unroll
        for (int b = 0; b < NB; b++) {
            float4 xb = *reinterpret_cast<const float4*>(&sX[(b0 + b) * ID]);
            #pragma unroll
            for (int g = 0; g < 4; g++) {
                float a = bias0[g] + w0x[g][0] * xb.x + w0x[g][1] * xb.y
                                   + w0x[g][2] * xb.z + w0x[g][3] * xb.w;
                acc0[g][b] = pack2(a, 0.f);
            }
        }
        #pragma unroll 8
        for (int k = 0; k < HD; k += 4) {
            ulonglong2 w[4], h[NB];
            #pragma unroll
            for (int g = 0; g < 4; g++)
                w[g] = *reinterpret_cast<const ulonglong2*>(&sW0[(u + 64 * g) * WP + k]);
            #pragma unroll
            for (int b = 0; b < NB; b++)
                h[b] = *reinterpret_cast<const ulonglong2*>(&sH0[(b0 + b) * WP + k]);
            #pragma unroll
            for (int g = 0; g < 4; g++)
                #pragma unroll
                for (int b = 0; b < NB; b++) {
                    ffma2(acc0[g][b], w[g].x, h[b].x);
                    ffma2(acc0[g][b], w[g].y, h[b].y);
                }
        }

        // ======== phase 1b : layer0 activations (MUFU) — overlaps with 1c ====
        float hnew0[NB];
        #pragma unroll
        for (int b = 0; b < NB; b++) {
            float gi = fsig   (red2(acc0[0][b]));
            float gf = fsig   (red2(acc0[1][b]));
            float gg = tanhapx(red2(acc0[2][b]));
            float go = fsig   (red2(acc0[3][b]));
            c0[b] = gf * c0[b] + gi * gg;
            hnew0[b] = go * tanhapx(c0[b]);
        }

        // ======== phase 1c : layer1 pass-B  acc1 = bias + Whh1*h1_{t-1} ======
        u64 acc1[4][NB];
        #pragma unroll
        for (int g = 0; g < 4; g++)
            #pragma unroll
            for (int b = 0; b < NB; b++) acc1[g][b] = pack2(bias1[g], 0.f);
        #pragma unroll 4
        for (int k = 0; k < HD; k += 4) {
            ulonglong2 w[4], h[NB];
            #pragma unroll
            for (int g = 0; g < 4; g++)
                w[g] = *reinterpret_cast<const ulonglong2*>(&sW1h[(u + 64 * g) * WP + k]);
            #pragma unroll
            for (int b = 0; b < NB; b++)
                h[b] = *reinterpret_cast<const ulonglong2*>(&sH1[(b0 + b) * WP + k]);
            #pragma unroll
            for (int g = 0; g < 4; g++)
                #pragma unroll
                for (int b = 0; b < NB; b++) {
                    ffma2(acc1[g][b], w[g].x, h[b].x);
                    ffma2(acc1[g][b], w[g].y, h[b].y);
                }
        }

        pairbar(barid);    // pair-mate done reading sH0 old, sH1 old, sX old
        #pragma unroll
        for (int b = 0; b < NB; b++) sH0[(b0 + b) * WP + u] = hnew0[b];
        if (lx < 4 * NB) sX[bpre * ID + ipre] = xpre;
        pairbar(barid);    // new h0_t (and x_{t+1}) visible within pair

        // ======== phase 2 : layer1 pass-A  acc1 += Wih1*h0_t =================
        #pragma unroll 8
        for (int k = 0; k < HD; k += 4) {
            ulonglong2 w[4], h[NB];
            #pragma unroll
            for (int g = 0; g < 4; g++)
                w[g] = *reinterpret_cast<const ulonglong2*>(&sW1i[(u + 64 * g) * WP + k]);
            #pragma unroll
            for (int b = 0; b < NB; b++)
                h[b] = *reinterpret_cast<const ulonglong2*>(&sH0[(b0 + b) * WP + k]);
            #pragma unroll
            for (int g = 0; g < 4; g++)
                #pragma unroll
                for (int b = 0; b < NB; b++) {
                    ffma2(acc1[g][b], w[g].x, h[b].x);
                    ffma2(acc1[g][b], w[g].y, h[b].y);
                }
        }
        float hnew1[NB];
        #pragma unroll
        for (int b = 0; b < NB; b++) {
            float gi = fsig   (red2(acc1[0][b]));
            float gf = fsig   (red2(acc1[1][b]));
            float gg = tanhapx(red2(acc1[2][b]));
            float go = fsig   (red2(acc1[3][b]));
            c1[b] = gf * c1[b] + gi * gg;
            hnew1[b] = go * tanhapx(c1[b]);
        }
        // sH1 old reads happened in phase 1c (before the two pairbars above)
        #pragma unroll
        for (int b = 0; b < NB; b++) sH1[(b0 + b) * WP + u] = hnew1[b];
        pairbar(barid);    // h1_t visible before next step's 1c
    }

    __syncthreads();       // all pairs done; final sH1 stable CTA-wide

    // ================= MLP head =================
    float* W1s = sW0;      // reuse: W1 transposed [k][n]
    for (int e = t; e < HD * HD; e += THREADS) {
        int n = e >> 6, k = e & 63;
        W1s[k * 64 + n] = W1[e];
    }
    __syncthreads();

    float bb1 = b1[u];
    float zv[NB];
    #pragma unroll
    for (int b = 0; b < NB; b++) {
        float s = bb1;
        #pragma unroll 8
        for (int k = 0; k < HD; k++)
            s += W1s[k * 64 + u] * sH1[(b0 + b) * WP + k];
        zv[b] = fmaxf(s, 0.f);
    }
    __syncthreads();
    float* sZ = sH0;       // reuse
    #pragma unroll
    for (int b = 0; b < NB; b++) sZ[(b0 + b) * WP + u] = zv[b];
    __syncthreads();

    for (int e = t; e < BT * 12; e += THREADS) {
        int b = e / 12, o = e % 12;
        if (bBase + b < BATCH) {
            float s = __ldg(&b2[o]);
            #pragma unroll 8
            for (int n = 0; n < HD; n++)
                s += __ldg(&W2[o * 64 + n]) * sZ[b * WP + n];
            out[(size_t)(bBase + b) * 12 + o] = s;
        }
    }
}

extern "C" void kernel_launch(void* const* d_in, const int* in_sizes, int n_in,
                              void* d_out, int out_size)
{
    (void)in_sizes; (void)n_in; (void)out_size;
    const size_t smem = (size_t)(3 * GD * WP + 2 * BT * WP + BT * ID) * sizeof(float);
    cudaFuncSetAttribute(weather_lstm_kernel,
                         cudaFuncAttributeMaxDynamicSharedMemorySize, (int)smem);
    weather_lstm_kernel<<<NGRID, THREADS, smem>>>(
        (const float*)d_in[0],
        (const float*)d_in[1],  (const float*)d_in[2],
        (const float*)d_in[3],  (const float*)d_in[4],
        (const float*)d_in[5],  (const float*)d_in[6],
        (const float*)d_in[7],  (const float*)d_in[8],
        (const float*)d_in[9],  (const float*)d_in[10],
        (const float*)d_in[11], (const float*)d_in[12],
        (float*)d_out);
}

// round 7
// speedup vs baseline: 2.0488x; 2.0488x over previous
#include <cuda_runtime.h>
#include <cuda_bf16.h>
#include <cstdint>

#define THREADS 256
#define BT      28
#define BATCH   4096
#define TT      168
#define NGRID   147

// smem byte offsets from 1024-aligned base
#define W0HI   0u        // Whh0 hi : [256 rows][128B] SW128
#define W0LO   32768u
#define W1HHI  65536u    // Whh1
#define W1HLO  98304u
#define W1IHI  131072u   // Wih1
#define W1ILO  163840u
#define H0T(p,s)  (196608u + ((p)*2u+(s))*4096u)   // h0 tiles [32][64] bf16
#define H1T(p,s)  (212992u + ((p)*2u+(s))*4096u)
#define SXO(p)    (229376u + (p)*512u)             // x fp32 [32][4]
#define SMEM_BYTES 231424

__device__ __forceinline__ uint32_t smem_u32(const void* p) {
    uint32_t a;
    asm("{ .reg .u64 t; cvta.to.shared.u64 t, %1; cvt.u32.u64 %0, t; }" : "=r"(a) : "l"(p));
    return a;
}
__device__ __forceinline__ float tanhapx(float x) {
    float y; asm("tanh.approx.f32 %0, %1;" : "=f"(y) : "f"(x)); return y;
}
__device__ __forceinline__ float fsig(float x) { return fmaf(0.5f, tanhapx(0.5f * x), 0.5f); }

__device__ __forceinline__ void ldsm4(uint32_t &r0, uint32_t &r1, uint32_t &r2, uint32_t &r3, uint32_t a) {
    asm volatile("ldmatrix.sync.aligned.m8n8.x4.shared.b16 {%0,%1,%2,%3}, [%4];"
                 : "=r"(r0), "=r"(r1), "=r"(r2), "=r"(r3) : "r"(a));
}
__device__ __forceinline__ void ldsm2(uint32_t &r0, uint32_t &r1, uint32_t a) {
    asm volatile("ldmatrix.sync.aligned.m8n8.x2.shared.b16 {%0,%1}, [%2];"
                 : "=r"(r0), "=r"(r1) : "r"(a));
}
__device__ __forceinline__ void mma_bf16(float &c0, float &c1, float &c2, float &c3,
                                         uint32_t a0, uint32_t a1, uint32_t a2, uint32_t a3,
                                         uint32_t b0, uint32_t b1) {
    asm volatile("mma.sync.aligned.m16n8k16.row.col.f32.bf16.bf16.f32 "
                 "{%0,%1,%2,%3}, {%4,%5,%6,%7}, {%8,%9}, {%0,%1,%2,%3};"
                 : "+f"(c0), "+f"(c1), "+f"(c2), "+f"(c3)
                 : "r"(a0), "r"(a1), "r"(a2), "r"(a3), "r"(b0), "r"(b1));
}

// 3-term bf16-split GEMM accumulate: acc[4 Mtiles][2 Ntiles][4 cregs]
//   += Ahi*Bhi + Ahi*Blo + Alo*Bhi   over 4 k16 chunks (K=64)
__device__ __forceinline__ void gemm3(float acc[4][2][4],
                                      uint32_t AhiB, uint32_t AloB,
                                      uint32_t BhiB, uint32_t BloB,
                                      const uint32_t* aRow, const uint32_t* bRow,
                                      uint32_t hbA, uint32_t xorA,
                                      uint32_t hbB, uint32_t xorB)
{
    #pragma unroll
    for (int kc = 0; kc < 4; kc++) {
        const uint32_t kA = ((uint32_t)(kc * 32) + hbA) ^ xorA;
        const uint32_t kB = ((uint32_t)(kc * 32) + hbB) ^ xorB;
        uint32_t ah[4][4], al[4][4], bh[2][2], bl[2][2];
        #pragma unroll
        for (int G = 0; G < 4; G++) {
            ldsm4(ah[G][0], ah[G][1], ah[G][2], ah[G][3], AhiB + aRow[G] + kA);
            ldsm4(al[G][0], al[G][1], al[G][2], al[G][3], AloB + aRow[G] + kA);
        }
        #pragma unroll
        for (int nt = 0; nt < 2; nt++) {
            ldsm2(bh[nt][0], bh[nt][1], BhiB + bRow[nt] + kB);
            ldsm2(bl[nt][0], bl[nt][1], BloB + bRow[nt] + kB);
        }
        #pragma unroll
        for (int G = 0; G < 4; G++)
            #pragma unroll
            for (int nt = 0; nt < 2; nt++) {
                mma_bf16(acc[G][nt][0], acc[G][nt][1], acc[G][nt][2], acc[G][nt][3],
                         ah[G][0], ah[G][1], ah[G][2], ah[G][3], bh[nt][0], bh[nt][1]);
                mma_bf16(acc[G][nt][0], acc[G][nt][1], acc[G][nt][2], acc[G][nt][3],
                         ah[G][0], ah[G][1], ah[G][2], ah[G][3], bl[nt][0], bl[nt][1]);
                mma_bf16(acc[G][nt][0], acc[G][nt][1], acc[G][nt][2], acc[G][nt][3],
                         al[G][0], al[G][1], al[G][2], al[G][3], bh[nt][0], bh[nt][1]);
            }
    }
}

extern "C" __global__ void __launch_bounds__(THREADS, 1)
weather_lstm_mma(const float* __restrict__ x,
                 const float* __restrict__ Wih0, const float* __restrict__ Whh0,
                 const float* __restrict__ bih0, const float* __restrict__ bhh0,
                 const float* __restrict__ Wih1, const float* __restrict__ Whh1,
                 const float* __restrict__ bih1, const float* __restrict__ bhh1,
                 const float* __restrict__ W1,  const float* __restrict__ b1,
                 const float* __restrict__ W2,  const float* __restrict__ b2,
                 float* __restrict__ out)
{
    extern __shared__ char smraw[];
    const uint32_t raw = smem_u32(smraw);
    const uint32_t BAu = (raw + 1023u) & ~1023u;
    char* BAc = smraw + (BAu - raw);

    const int t    = threadIdx.x;
    const int w    = t >> 5, lane = t & 31;
    const int m    = w >> 1, nh = w & 1;
    const int g4   = lane >> 2, t4 = lane & 3;
    const int u0   = m * 16 + g4;            // thread's units: u0, u0+8
    const int bBase = blockIdx.x * BT;

    // ldmatrix lane-invariant address parts
    const int      rlA  = (lane & 7) + ((lane >> 3) & 1) * 8;
    const uint32_t hbA  = (uint32_t)(((lane >> 4) & 1) * 16);
    const uint32_t xorA = (uint32_t)((lane & 7) << 4);
    const int      laneB = lane & 15;
    const int      rlB  = laneB & 7;
    const uint32_t hbB  = (uint32_t)(((laneB >> 3) & 1) * 16);
    const uint32_t xorB = (uint32_t)((laneB & 7) << 4);

    uint32_t aRow[4], bRow[2];
    #pragma unroll
    for (int G = 0; G < 4; G++) aRow[G] = (uint32_t)((G * 64 + m * 16 + rlA) * 128);
    #pragma unroll
    for (int nt = 0; nt < 2; nt++) bRow[nt] = (uint32_t)((nh * 16 + nt * 8 + rlB) * 128);

    // ---- preload weights: fp32 -> bf16 hi/lo, SW128 row-major [256][64] ----
    for (int e = t; e < 256 * 64; e += THREADS) {
        int j = e >> 6, k = e & 63;
        uint32_t off = ((uint32_t)(j * 128 + k * 2)) ^ ((uint32_t)(j & 7) << 4);
        float v0 = Whh0[e], v1 = Whh1[e], v2 = Wih1[e];
        __nv_bfloat16 h0 = __float2bfloat16(v0);
        __nv_bfloat16 h1 = __float2bfloat16(v1);
        __nv_bfloat16 h2 = __float2bfloat16(v2);
        *(__nv_bfloat16*)(BAc + W0HI  + off) = h0;
        *(__nv_bfloat16*)(BAc + W0LO  + off) = __float2bfloat16(v0 - __bfloat162float(h0));
        *(__nv_bfloat16*)(BAc + W1HHI + off) = h1;
        *(__nv_bfloat16*)(BAc + W1HLO + off) = __float2bfloat16(v1 - __bfloat162float(h1));
        *(__nv_bfloat16*)(BAc + W1IHI + off) = h2;
        *(__nv_bfloat16*)(BAc + W1ILO + off) = __float2bfloat16(v2 - __bfloat162float(h2));
    }
    // zero all h tiles (32KB) and x buffers
    for (int e = t; e < 8192; e += THREADS) ((uint32_t*)(BAc + H0T(0, 0)))[e] = 0u;
    for (int e = t; e < 256;  e += THREADS) ((float*)(BAc + SXO(0)))[e] = 0.f;

    const int xb = t >> 2, xq = t & 3;
    const bool xok = (t < 112) && (bBase + xb < BATCH);
    if (xok) ((float*)(BAc + SXO(0)))[xb * 4 + xq] = x[(size_t)(bBase + xb) * TT * 4 + xq];

    // per-thread constants
    float bias0[4][2], bias1[4][2], w0x[2][4][4];
    #pragma unroll
    for (int G = 0; G < 4; G++)
        #pragma unroll
        for (int uh = 0; uh < 2; uh++) {
            int j = G * 64 + u0 + uh * 8;
            bias0[G][uh] = bih0[j] + bhh0[j];
            bias1[G][uh] = bih1[j] + bhh1[j];
            #pragma unroll
            for (int q = 0; q < 4; q++) w0x[uh][G][q] = Wih0[j * 4 + q];
        }
    float c0s[2][2][2], c1s[2][2][2], hlast[2][2][2];
    #pragma unroll
    for (int i = 0; i < 2; i++)
        #pragma unroll
        for (int jj = 0; jj < 2; jj++)
            #pragma unroll
            for (int kk = 0; kk < 2; kk++) { c0s[i][jj][kk] = 0.f; c1s[i][jj][kk] = 0.f; hlast[i][jj][kk] = 0.f; }

    __syncthreads();

    for (int step = 0; step < TT; step++) {
        const int p = step & 1;
        float xpre = 0.f;
        if (xok && step + 1 < TT)
            xpre = x[((size_t)(bBase + xb) * TT + step + 1) * 4 + xq];

        // ---- phase 1: D0 = Whh0 (x) h0[p]  (3-term bf16 split) ----
        float acc0[4][2][4];
        #pragma unroll
        for (int G = 0; G < 4; G++)
            #pragma unroll
            for (int nt = 0; nt < 2; nt++)
                #pragma unroll
                for (int c = 0; c < 4; c++) acc0[G][nt][c] = 0.f;
        gemm3(acc0, BAu + W0HI, BAu + W0LO, BAu + H0T(p, 0), BAu + H0T(p, 1),
              aRow, bRow, hbA, xorA, hbB, xorB);

        // act0: add bias + Wih0*x (scalar), LSTM cell, write h0_t -> buf p^1
        #pragma unroll
        for (int nt = 0; nt < 2; nt++)
            #pragma unroll
            for (int ch = 0; ch < 2; ch++) {
                const int b = nh * 16 + nt * 8 + 2 * t4 + ch;
                const float4 xv = *(const float4*)(BAc + SXO(p) + b * 16);
                #pragma unroll
                for (int uh = 0; uh < 2; uh++) {
                    float pre[4];
                    #pragma unroll
                    for (int G = 0; G < 4; G++)
                        pre[G] = acc0[G][nt][uh * 2 + ch] + bias0[G][uh]
                               + w0x[uh][G][0] * xv.x + w0x[uh][G][1] * xv.y
                               + w0x[uh][G][2] * xv.z + w0x[uh][G][3] * xv.w;
                    float gi = fsig(pre[0]), gf = fsig(pre[1]);
                    float gg = tanhapx(pre[2]), go = fsig(pre[3]);
                    float &c = c0s[nt][uh][ch];
                    c = gf * c + gi * gg;
                    float h = go * tanhapx(c);
                    const int u = u0 + uh * 8;
                    uint32_t off = ((uint32_t)(b * 128 + u * 2)) ^ ((uint32_t)(b & 7) << 4);
                    __nv_bfloat16 hh = __float2bfloat16(h);
                    *(__nv_bfloat16*)(BAc + H0T(p ^ 1, 0) + off) = hh;
                    *(__nv_bfloat16*)(BAc + H0T(p ^ 1, 1) + off) = __float2bfloat16(h - __bfloat162float(hh));
                }
            }
        if (t < 112) ((float*)(BAc + SXO(p ^ 1)))[xb * 4 + xq] = xpre;
        __syncthreads();

        // ---- phase 2: D1 = Whh1 (x) h1[p] + Wih1 (x) h0[p^1] ----
        float acc1[4][2][4];
        #pragma unroll
        for (int G = 0; G < 4; G++)
            #pragma unroll
            for (int nt = 0; nt < 2; nt++)
                #pragma unroll
                for (int c = 0; c < 4; c++) acc1[G][nt][c] = 0.f;
        gemm3(acc1, BAu + W1HHI, BAu + W1HLO, BAu + H1T(p, 0), BAu + H1T(p, 1),
              aRow, bRow, hbA, xorA, hbB, xorB);
        gemm3(acc1, BAu + W1IHI, BAu + W1ILO, BAu + H0T(p ^ 1, 0), BAu + H0T(p ^ 1, 1),
              aRow, bRow, hbA, xorA, hbB, xorB);

        #pragma unroll
        for (int nt = 0; nt < 2; nt++)
            #pragma unroll
            for (int ch = 0; ch < 2; ch++) {
                const int b = nh * 16 + nt * 8 + 2 * t4 + ch;
                #pragma unroll
                for (int uh = 0; uh < 2; uh++) {
                    float pre[4];
                    #pragma unroll
                    for (int G = 0; G < 4; G++)
                        pre[G] = acc1[G][nt][uh * 2 + ch] + bias1[G][uh];
                    float gi = fsig(pre[0]), gf = fsig(pre[1]);
                    float gg = tanhapx(pre[2]), go = fsig(pre[3]);
                    float &c = c1s[nt][uh][ch];
                    c = gf * c + gi * gg;
                    float h = go * tanhapx(c);
                    hlast[nt][uh][ch] = h;
                    const int u = u0 + uh * 8;
                    uint32_t off = ((uint32_t)(b * 128 + u * 2)) ^ ((uint32_t)(b & 7) << 4);
                    __nv_bfloat16 hh = __float2bfloat16(h);
                    *(__nv_bfloat16*)(BAc + H1T(p ^ 1, 0) + off) = hh;
                    *(__nv_bfloat16*)(BAc + H1T(p ^ 1, 1) + off) = __float2bfloat16(h - __bfloat162float(hh));
                }
            }
        __syncthreads();
    }

    // ---- stage final fp32 h1 into (dead) weight region ----
    float* hs = (float*)BAc;                       // [32][64] fp32
    #pragma unroll
    for (int nt = 0; nt < 2; nt++)
        #pragma unroll
        for (int ch = 0; ch < 2; ch++) {
            const int b = nh * 16 + nt * 8 + 2 * t4 + ch;
            #pragma unroll
            for (int uh = 0; uh < 2; uh++)
                hs[b * 64 + u0 + uh * 8] = hlast[nt][uh][ch];
        }
    float* W1s = (float*)(BAc + 16384);            // W1 transposed [k][n]
    for (int e = t; e < 64 * 64; e += THREADS) {
        int n = e >> 6, k = e & 63;
        W1s[k * 64 + n] = W1[e];
    }
    __syncthreads();

    const int u2 = t & 63, pid = t >> 6;
    float bb = b1[u2];
    float zv[7];
    #pragma unroll
    for (int b = 0; b < 7; b++) {
        int row = pid * 7 + b;
        float sum = bb;
        #pragma unroll 8
        for (int k = 0; k < 64; k++)
            sum += W1s[k * 64 + u2] * hs[row * 64 + k];
        zv[b] = fmaxf(sum, 0.f);
    }
    __syncthreads();
    float* sZ = (float*)(BAc + 36864);             // [28][64]
    #pragma unroll
    for (int b = 0; b < 7; b++) sZ[(pid * 7 + b) * 64 + u2] = zv[b];
    __syncthreads();

    for (int e = t; e < BT * 12; e += THREADS) {
        int b = e / 12, o = e % 12;
        if (bBase + b < BATCH) {
            float sum = __ldg(&b2[o]);
            #pragma unroll 8
            for (int n = 0; n < 64; n++)
                sum += __ldg(&W2[o * 64 + n]) * sZ[b * 64 + n];
            out[(size_t)(bBase + b) * 12 + o] = sum;
        }
    }
}

extern "C" void kernel_launch(void* const* d_in, const int* in_sizes, int n_in,
                              void* d_out, int out_size)
{
    (void)in_sizes; (void)n_in; (void)out_size;
    cudaFuncSetAttribute(weather_lstm_mma,
                         cudaFuncAttributeMaxDynamicSharedMemorySize, SMEM_BYTES);
    weather_lstm_mma<<<NGRID, THREADS, SMEM_BYTES>>>(
        (const float*)d_in[0],
        (const float*)d_in[1],  (const float*)d_in[2],
        (const float*)d_in[3],  (const float*)d_in[4],
        (const float*)d_in[5],  (const float*)d_in[6],
        (const float*)d_in[7],  (const float*)d_in[8],
        (const float*)d_in[9],  (const float*)d_in[10],
        (const float*)d_in[11], (const float*)d_in[12],
        (float*)d_out);
}

// round 8
// speedup vs baseline: 2.2399x; 1.0933x over previous
#include <cuda_runtime.h>
#include <cuda_bf16.h>
#include <cstdint>

#define THREADS 256
#define BT      28
#define BATCH   4096
#define TT      168
#define NGRID   147

// smem byte offsets from 1024-aligned base
#define W0HI   0u        // Whh0 hi : [256 rows][128B] SW128
#define W0LO   32768u
#define W1HHI  65536u    // Whh1
#define W1HLO  98304u
#define W1IHI  131072u   // Wih1
#define W1ILO  163840u
#define H0T(p,s)  (196608u + ((p)*2u+(s))*4096u)   // h0 tiles [32][64] bf16
#define H1T(p,s)  (212992u + ((p)*2u+(s))*4096u)
#define HS_OFF    (212992u + 8192u)                // fp32 h1 staging (aliases H1T(1,*))
#define SXO(p)    (229376u + (p)*512u)             // x fp32 [32][4]
#define SMEM_BYTES 231424

__device__ __forceinline__ uint32_t smem_u32(const void* p) {
    uint32_t a;
    asm("{ .reg .u64 t; cvta.to.shared.u64 t, %1; cvt.u32.u64 %0, t; }" : "=r"(a) : "l"(p));
    return a;
}
__device__ __forceinline__ float tanhapx(float x) {
    float y; asm("tanh.approx.f32 %0, %1;" : "=f"(y) : "f"(x)); return y;
}
__device__ __forceinline__ float fsig(float x) { return fmaf(0.5f, tanhapx(0.5f * x), 0.5f); }

__device__ __forceinline__ void ldsm4(uint32_t &r0, uint32_t &r1, uint32_t &r2, uint32_t &r3, uint32_t a) {
    asm volatile("ldmatrix.sync.aligned.m8n8.x4.shared.b16 {%0,%1,%2,%3}, [%4];"
                 : "=r"(r0), "=r"(r1), "=r"(r2), "=r"(r3) : "r"(a));
}
__device__ __forceinline__ void ldsm2(uint32_t &r0, uint32_t &r1, uint32_t a) {
    asm volatile("ldmatrix.sync.aligned.m8n8.x2.shared.b16 {%0,%1}, [%2];"
                 : "=r"(r0), "=r"(r1) : "r"(a));
}
__device__ __forceinline__ void mma_bf16(float &c0, float &c1, float &c2, float &c3,
                                         uint32_t a0, uint32_t a1, uint32_t a2, uint32_t a3,
                                         uint32_t b0, uint32_t b1) {
    asm volatile("mma.sync.aligned.m16n8k16.row.col.f32.bf16.bf16.f32 "
                 "{%0,%1,%2,%3}, {%4,%5,%6,%7}, {%8,%9}, {%0,%1,%2,%3};"
                 : "+f"(c0), "+f"(c1), "+f"(c2), "+f"(c3)
                 : "r"(a0), "r"(a1), "r"(a2), "r"(a3), "r"(b0), "r"(b1));
}

// 3-term bf16-split GEMM accumulate over K=64 (4 k16 chunks):
//   acc += Ahi*Bhi + Ahi*Blo + Alo*Bhi
__device__ __forceinline__ void gemm3(float acc[4][2][4],
                                      uint32_t AhiB, uint32_t AloB,
                                      uint32_t BhiB, uint32_t BloB,
                                      const uint32_t* aRow, const uint32_t* bRow,
                                      uint32_t hbA, uint32_t xorA,
                                      uint32_t hbB, uint32_t xorB)
{
    #pragma unroll
    for (int kc = 0; kc < 4; kc++) {
        const uint32_t kA = ((uint32_t)(kc * 32) + hbA) ^ xorA;
        const uint32_t kB = ((uint32_t)(kc * 32) + hbB) ^ xorB;
        uint32_t ah[4][4], al[4][4], bh[2][2], bl[2][2];
        #pragma unroll
        for (int G = 0; G < 4; G++) {
            ldsm4(ah[G][0], ah[G][1], ah[G][2], ah[G][3], AhiB + aRow[G] + kA);
            ldsm4(al[G][0], al[G][1], al[G][2], al[G][3], AloB + aRow[G] + kA);
        }
        #pragma unroll
        for (int nt = 0; nt < 2; nt++) {
            ldsm2(bh[nt][0], bh[nt][1], BhiB + bRow[nt] + kB);
            ldsm2(bl[nt][0], bl[nt][1], BloB + bRow[nt] + kB);
        }
        #pragma unroll
        for (int G = 0; G < 4; G++)
            #pragma unroll
            for (int nt = 0; nt < 2; nt++) {
                mma_bf16(acc[G][nt][0], acc[G][nt][1], acc[G][nt][2], acc[G][nt][3],
                         ah[G][0], ah[G][1], ah[G][2], ah[G][3], bh[nt][0], bh[nt][1]);
                mma_bf16(acc[G][nt][0], acc[G][nt][1], acc[G][nt][2], acc[G][nt][3],
                         ah[G][0], ah[G][1], ah[G][2], ah[G][3], bl[nt][0], bl[nt][1]);
                mma_bf16(acc[G][nt][0], acc[G][nt][1], acc[G][nt][2], acc[G][nt][3],
                         al[G][0], al[G][1], al[G][2], al[G][3], bh[nt][0], bh[nt][1]);
            }
    }
}

extern "C" __global__ void __launch_bounds__(THREADS, 1)
weather_lstm_mma(const float* __restrict__ x,
                 const float* __restrict__ Wih0, const float* __restrict__ Whh0,
                 const float* __restrict__ bih0, const float* __restrict__ bhh0,
                 const float* __restrict__ Wih1, const float* __restrict__ Whh1,
                 const float* __restrict__ bih1, const float* __restrict__ bhh1,
                 const float* __restrict__ W1,  const float* __restrict__ b1,
                 const float* __restrict__ W2,  const float* __restrict__ b2,
                 float* __restrict__ out)
{
    extern __shared__ char smraw[];
    const uint32_t raw = smem_u32(smraw);
    const uint32_t BAu = (raw + 1023u) & ~1023u;
    char* BAc = smraw + (BAu - raw);

    const int t    = threadIdx.x;
    const int w    = t >> 5, lane = t & 31;
    const int m    = w >> 1, nh = w & 1;
    const int g4   = lane >> 2, t4 = lane & 3;
    const int u0   = m * 16 + g4;
    const int bBase = blockIdx.x * BT;

    const int      rlA  = (lane & 7) + ((lane >> 3) & 1) * 8;
    const uint32_t hbA  = (uint32_t)(((lane >> 4) & 1) * 16);
    const uint32_t xorA = (uint32_t)((lane & 7) << 4);
    const int      laneB = lane & 15;
    const int      rlB  = laneB & 7;
    const uint32_t hbB  = (uint32_t)(((laneB >> 3) & 1) * 16);
    const uint32_t xorB = (uint32_t)((laneB & 7) << 4);

    uint32_t aRow[4], bRow[2];
    #pragma unroll
    for (int G = 0; G < 4; G++) aRow[G] = (uint32_t)((G * 64 + m * 16 + rlA) * 128);
    #pragma unroll
    for (int nt = 0; nt < 2; nt++) bRow[nt] = (uint32_t)((nh * 16 + nt * 8 + rlB) * 128);

    // ---- preload weights: fp32 -> bf16 hi/lo, SW128 row-major [256][64] ----
    for (int e = t; e < 256 * 64; e += THREADS) {
        int j = e >> 6, k = e & 63;
        uint32_t off = ((uint32_t)(j * 128 + k * 2)) ^ ((uint32_t)(j & 7) << 4);
        float v0 = Whh0[e], v1 = Whh1[e], v2 = Wih1[e];
        __nv_bfloat16 h0 = __float2bfloat16(v0);
        __nv_bfloat16 h1 = __float2bfloat16(v1);
        __nv_bfloat16 h2 = __float2bfloat16(v2);
        *(__nv_bfloat16*)(BAc + W0HI  + off) = h0;
        *(__nv_bfloat16*)(BAc + W0LO  + off) = __float2bfloat16(v0 - __bfloat162float(h0));
        *(__nv_bfloat16*)(BAc + W1HHI + off) = h1;
        *(__nv_bfloat16*)(BAc + W1HLO + off) = __float2bfloat16(v1 - __bfloat162float(h1));
        *(__nv_bfloat16*)(BAc + W1IHI + off) = h2;
        *(__nv_bfloat16*)(BAc + W1ILO + off) = __float2bfloat16(v2 - __bfloat162float(h2));
    }
    // zero all h tiles (32KB) and x buffers
    for (int e = t; e < 8192; e += THREADS) ((uint32_t*)(BAc + H0T(0, 0)))[e] = 0u;
    for (int e = t; e < 256;  e += THREADS) ((float*)(BAc + SXO(0)))[e] = 0.f;

    const int xb = t >> 2, xq = t & 3;
    const bool xok = (t < 112) && (bBase + xb < BATCH);
    if (xok) ((float*)(BAc + SXO(0)))[xb * 4 + xq] = x[(size_t)(bBase + xb) * TT * 4 + xq];

    float bias0[4][2], bias1[4][2], w0x[2][4][4];
    #pragma unroll
    for (int G = 0; G < 4; G++)
        #pragma unroll
        for (int uh = 0; uh < 2; uh++) {
            int j = G * 64 + u0 + uh * 8;
            bias0[G][uh] = bih0[j] + bhh0[j];
            bias1[G][uh] = bih1[j] + bhh1[j];
            #pragma unroll
            for (int q = 0; q < 4; q++) w0x[uh][G][q] = Wih0[j * 4 + q];
        }
    float c0s[2][2][2], c1s[2][2][2];
    #pragma unroll
    for (int i = 0; i < 2; i++)
        #pragma unroll
        for (int jj = 0; jj < 2; jj++)
            #pragma unroll
            for (int kk = 0; kk < 2; kk++) { c0s[i][jj][kk] = 0.f; c1s[i][jj][kk] = 0.f; }

    __syncthreads();

    // Wavefront: iter ts computes h0[ts] (if ts<TT) and h1[ts-1] (if ts>0).
    // Buffers at iter start (p = ts&1): h0T(p) = h0[ts-1], h1T(p) = h1[ts-2], sX(p) = x[ts].
    #pragma unroll 1
    for (int ts = 0; ts <= TT; ts++) {
        const int p = ts & 1;
        float xpre = 0.f;
        if (xok && ts + 1 < TT)
            xpre = x[((size_t)(bBase + xb) * TT + ts + 1) * 4 + xq];

        // ===== layer 1 (step ts-1): acc1 = Whh1*h1[ts-2] + Wih1*h0[ts-1] =====
        if (ts > 0) {
            float acc1[4][2][4];
            #pragma unroll
            for (int G = 0; G < 4; G++)
                #pragma unroll
                for (int nt = 0; nt < 2; nt++)
                    #pragma unroll
                    for (int c = 0; c < 4; c++) acc1[G][nt][c] = 0.f;
            gemm3(acc1, BAu + W1HHI, BAu + W1HLO, BAu + H1T(p, 0), BAu + H1T(p, 1),
                  aRow, bRow, hbA, xorA, hbB, xorB);
            gemm3(acc1, BAu + W1IHI, BAu + W1ILO, BAu + H0T(p, 0), BAu + H0T(p, 1),
                  aRow, bRow, hbA, xorA, hbB, xorB);

            #pragma unroll
            for (int nt = 0; nt < 2; nt++)
                #pragma unroll
                for (int ch = 0; ch < 2; ch++) {
                    const int b = nh * 16 + nt * 8 + 2 * t4 + ch;
                    #pragma unroll
                    for (int uh = 0; uh < 2; uh++) {
                        float pre[4];
                        #pragma unroll
                        for (int G = 0; G < 4; G++)
                            pre[G] = acc1[G][nt][uh * 2 + ch] + bias1[G][uh];
                        float gi = fsig(pre[0]), gf = fsig(pre[1]);
                        float gg = tanhapx(pre[2]), go = fsig(pre[3]);
                        float &c = c1s[nt][uh][ch];
                        c = gf * c + gi * gg;
                        float h = go * tanhapx(c);
                        const int u = u0 + uh * 8;
                        if (ts < TT) {
                            uint32_t off = ((uint32_t)(b * 128 + u * 2)) ^ ((uint32_t)(b & 7) << 4);
                            __nv_bfloat16 hh = __float2bfloat16(h);
                            *(__nv_bfloat16*)(BAc + H1T(p ^ 1, 0) + off) = hh;
                            *(__nv_bfloat16*)(BAc + H1T(p ^ 1, 1) + off) =
                                __float2bfloat16(h - __bfloat162float(hh));
                        } else {
                            ((float*)(BAc + HS_OFF))[b * 64 + u] = h;  // final h1 fp32
                        }
                    }
                }
        }

        // ===== layer 0 (step ts): acc0 = Whh0*h0[ts-1]; act adds Wih0*x[ts] =====
        if (ts < TT) {
            float acc0[4][2][4];
            #pragma unroll
            for (int G = 0; G < 4; G++)
                #pragma unroll
                for (int nt = 0; nt < 2; nt++)
                    #pragma unroll
                    for (int c = 0; c < 4; c++) acc0[G][nt][c] = 0.f;
            gemm3(acc0, BAu + W0HI, BAu + W0LO, BAu + H0T(p, 0), BAu + H0T(p, 1),
                  aRow, bRow, hbA, xorA, hbB, xorB);

            #pragma unroll
            for (int nt = 0; nt < 2; nt++)
                #pragma unroll
                for (int ch = 0; ch < 2; ch++) {
                    const int b = nh * 16 + nt * 8 + 2 * t4 + ch;
                    const float4 xv = *(const float4*)(BAc + SXO(p) + b * 16);
                    #pragma unroll
                    for (int uh = 0; uh < 2; uh++) {
                        float pre[4];
                        #pragma unroll
                        for (int G = 0; G < 4; G++)
                            pre[G] = acc0[G][nt][uh * 2 + ch] + bias0[G][uh]
                                   + w0x[uh][G][0] * xv.x + w0x[uh][G][1] * xv.y
                                   + w0x[uh][G][2] * xv.z + w0x[uh][G][3] * xv.w;
                        float gi = fsig(pre[0]), gf = fsig(pre[1]);
                        float gg = tanhapx(pre[2]), go = fsig(pre[3]);
                        float &c = c0s[nt][uh][ch];
                        c = gf * c + gi * gg;
                        float h = go * tanhapx(c);
                        const int u = u0 + uh * 8;
                        uint32_t off = ((uint32_t)(b * 128 + u * 2)) ^ ((uint32_t)(b & 7) << 4);
                        __nv_bfloat16 hh = __float2bfloat16(h);
                        *(__nv_bfloat16*)(BAc + H0T(p ^ 1, 0) + off) = hh;
                        *(__nv_bfloat16*)(BAc + H0T(p ^ 1, 1) + off) =
                            __float2bfloat16(h - __bfloat162float(hh));
                    }
                }
            if (t < 112) ((float*)(BAc + SXO(p ^ 1)))[xb * 4 + xq] = xpre;
        }

        __syncthreads();   // single barrier per iteration
    }

    // ================= MLP head =================
    const float* hs = (const float*)(BAc + HS_OFF);   // fp32 h1 final [32][64]
    float* W1s = (float*)(BAc + 16384);               // W1^T in dead weight region
    for (int e = t; e < 64 * 64; e += THREADS) {
        int n = e >> 6, k = e & 63;
        W1s[k * 64 + n] = W1[e];
    }
    __syncthreads();

    const int u2 = t & 63, pid = t >> 6;
    float bb = b1[u2];
    float zv[7];
    #pragma unroll
    for (int b = 0; b < 7; b++) {
        int row = pid * 7 + b;
        float sum = bb;
        #pragma unroll 8
        for (int k = 0; k < 64; k++)
            sum += W1s[k * 64 + u2] * hs[row * 64 + k];
        zv[b] = fmaxf(sum, 0.f);
    }
    __syncthreads();
    float* sZ = (float*)(BAc + 36864);
    #pragma unroll
    for (int b = 0; b < 7; b++) sZ[(pid * 7 + b) * 64 + u2] = zv[b];
    __syncthreads();

    for (int e = t; e < BT * 12; e += THREADS) {
        int b = e / 12, o = e % 12;
        if (bBase + b < BATCH) {
            float sum = __ldg(&b2[o]);
            #pragma unroll 8
            for (int n = 0; n < 64; n++)
                sum += __ldg(&W2[o * 64 + n]) * sZ[b * 64 + n];
            out[(size_t)(bBase + b) * 12 + o] = sum;
        }
    }
}

extern "C" void kernel_launch(void* const* d_in, const int* in_sizes, int n_in,
                              void* d_out, int out_size)
{
    (void)in_sizes; (void)n_in; (void)out_size;
    cudaFuncSetAttribute(weather_lstm_mma,
                         cudaFuncAttributeMaxDynamicSharedMemorySize, SMEM_BYTES);
    weather_lstm_mma<<<NGRID, THREADS, SMEM_BYTES>>>(
        (const float*)d_in[0],
        (const float*)d_in[1],  (const float*)d_in[2],
        (const float*)d_in[3],  (const float*)d_in[4],
        (const float*)d_in[5],  (const float*)d_in[6],
        (const float*)d_in[7],  (const float*)d_in[8],
        (const float*)d_in[9],  (const float*)d_in[10],
        (const float*)d_in[11], (const float*)d_in[12],
        (float*)d_out);
}

// round 9
// speedup vs baseline: 3.0207x; 1.3486x over previous
#include <cuda_runtime.h>
#include <cuda_fp16.h>
#include <cstdint>

#define THREADS 256
#define BT      28
#define BATCH   4096
#define TT      168
#define NGRID   147

// smem byte offsets from 1024-aligned base
#define W0F    0u        // Whh0 fp16 : [256 rows][128B] SW128 (64 cols fp16)
#define W1HF   32768u    // Whh1
#define W1IF   65536u    // Wih1
#define H0T(p,s)  (98304u  + ((p)*2u+(s))*4096u)   // h0 tiles [32][64] fp16 (s: hi/lo)
#define H1T(p,s)  (114688u + ((p)*2u+(s))*4096u)
#define HS_OFF    (114688u + 8192u)                // fp32 h1 staging (aliases H1T(1,*))
#define SXO(p)    (131072u + (p)*512u)             // x fp32 [32][4]
#define SMEM_BYTES 133120

__device__ __forceinline__ uint32_t smem_u32(const void* p) {
    uint32_t a;
    asm("{ .reg .u64 t; cvta.to.shared.u64 t, %1; cvt.u32.u64 %0, t; }" : "=r"(a) : "l"(p));
    return a;
}
__device__ __forceinline__ float tanhapx(float x) {
    float y; asm("tanh.approx.f32 %0, %1;" : "=f"(y) : "f"(x)); return y;
}
__device__ __forceinline__ float fsig(float x) { return fmaf(0.5f, tanhapx(0.5f * x), 0.5f); }

__device__ __forceinline__ void ldsm4(uint32_t &r0, uint32_t &r1, uint32_t &r2, uint32_t &r3, uint32_t a) {
    asm volatile("ldmatrix.sync.aligned.m8n8.x4.shared.b16 {%0,%1,%2,%3}, [%4];"
                 : "=r"(r0), "=r"(r1), "=r"(r2), "=r"(r3) : "r"(a));
}
__device__ __forceinline__ void ldsm2(uint32_t &r0, uint32_t &r1, uint32_t a) {
    asm volatile("ldmatrix.sync.aligned.m8n8.x2.shared.b16 {%0,%1}, [%2];"
                 : "=r"(r0), "=r"(r1) : "r"(a));
}
__device__ __forceinline__ void mma_f16(float &c0, float &c1, float &c2, float &c3,
                                        uint32_t a0, uint32_t a1, uint32_t a2, uint32_t a3,
                                        uint32_t b0, uint32_t b1) {
    asm volatile("mma.sync.aligned.m16n8k16.row.col.f32.f16.f16.f32 "
                 "{%0,%1,%2,%3}, {%4,%5,%6,%7}, {%8,%9}, {%0,%1,%2,%3};"
                 : "+f"(c0), "+f"(c1), "+f"(c2), "+f"(c3)
                 : "r"(a0), "r"(a1), "r"(a2), "r"(a3), "r"(b0), "r"(b1));
}

// fp16 2-term GEMM accumulate over K=64 (4 k16 chunks): acc += A*(Bhi + Blo)
__device__ __forceinline__ void gemm2(float acc[4][2][4],
                                      uint32_t AB,
                                      uint32_t BhiB, uint32_t BloB,
                                      const uint32_t* aRow, const uint32_t* bRow,
                                      uint32_t hbA, uint32_t xorA,
                                      uint32_t hbB, uint32_t xorB)
{
    #pragma unroll
    for (int kc = 0; kc < 4; kc++) {
        const uint32_t kA = ((uint32_t)(kc * 32) + hbA) ^ xorA;
        const uint32_t kB = ((uint32_t)(kc * 32) + hbB) ^ xorB;
        uint32_t ah[4][4], bh[2][2], bl[2][2];
        #pragma unroll
        for (int G = 0; G < 4; G++)
            ldsm4(ah[G][0], ah[G][1], ah[G][2], ah[G][3], AB + aRow[G] + kA);
        #pragma unroll
        for (int nt = 0; nt < 2; nt++) {
            ldsm2(bh[nt][0], bh[nt][1], BhiB + bRow[nt] + kB);
            ldsm2(bl[nt][0], bl[nt][1], BloB + bRow[nt] + kB);
        }
        #pragma unroll
        for (int G = 0; G < 4; G++)
            #pragma unroll
            for (int nt = 0; nt < 2; nt++) {
                mma_f16(acc[G][nt][0], acc[G][nt][1], acc[G][nt][2], acc[G][nt][3],
                        ah[G][0], ah[G][1], ah[G][2], ah[G][3], bh[nt][0], bh[nt][1]);
                mma_f16(acc[G][nt][0], acc[G][nt][1], acc[G][nt][2], acc[G][nt][3],
                        ah[G][0], ah[G][1], ah[G][2], ah[G][3], bl[nt][0], bl[nt][1]);
            }
    }
}

extern "C" __global__ void __launch_bounds__(THREADS, 1)
weather_lstm_mma(const float* __restrict__ x,
                 const float* __restrict__ Wih0, const float* __restrict__ Whh0,
                 const float* __restrict__ bih0, const float* __restrict__ bhh0,
                 const float* __restrict__ Wih1, const float* __restrict__ Whh1,
                 const float* __restrict__ bih1, const float* __restrict__ bhh1,
                 const float* __restrict__ W1,  const float* __restrict__ b1,
                 const float* __restrict__ W2,  const float* __restrict__ b2,
                 float* __restrict__ out)
{
    extern __shared__ char smraw[];
    const uint32_t raw = smem_u32(smraw);
    const uint32_t BAu = (raw + 1023u) & ~1023u;
    char* BAc = smraw + (BAu - raw);

    const int t    = threadIdx.x;
    const int w    = t >> 5, lane = t & 31;
    const int m    = w >> 1, nh = w & 1;
    const int g4   = lane >> 2, t4 = lane & 3;
    const int u0   = m * 16 + g4;
    const int bBase = blockIdx.x * BT;

    const int      rlA  = (lane & 7) + ((lane >> 3) & 1) * 8;
    const uint32_t hbA  = (uint32_t)(((lane >> 4) & 1) * 16);
    const uint32_t xorA = (uint32_t)((lane & 7) << 4);
    const int      laneB = lane & 15;
    const int      rlB  = laneB & 7;
    const uint32_t hbB  = (uint32_t)(((laneB >> 3) & 1) * 16);
    const uint32_t xorB = (uint32_t)((laneB & 7) << 4);

    uint32_t aRow[4], bRow[2];
    #pragma unroll
    for (int G = 0; G < 4; G++) aRow[G] = (uint32_t)((G * 64 + m * 16 + rlA) * 128);
    #pragma unroll
    for (int nt = 0; nt < 2; nt++) bRow[nt] = (uint32_t)((nh * 16 + nt * 8 + rlB) * 128);

    // ---- preload weights: fp32 -> fp16 (single, rounded), SW128 [256][64] ----
    for (int e = t; e < 256 * 64; e += THREADS) {
        int j = e >> 6, k = e & 63;
        uint32_t off = ((uint32_t)(j * 128 + k * 2)) ^ ((uint32_t)(j & 7) << 4);
        *(__half*)(BAc + W0F  + off) = __float2half_rn(Whh0[e]);
        *(__half*)(BAc + W1HF + off) = __float2half_rn(Whh1[e]);
        *(__half*)(BAc + W1IF + off) = __float2half_rn(Wih1[e]);
    }
    // zero all h tiles (32KB) and x buffers
    for (int e = t; e < 8192; e += THREADS) ((uint32_t*)(BAc + H0T(0, 0)))[e] = 0u;
    for (int e = t; e < 256;  e += THREADS) ((float*)(BAc + SXO(0)))[e] = 0.f;

    const int xb = t >> 2, xq = t & 3;
    const bool xok = (t < 112) && (bBase + xb < BATCH);
    if (xok) ((float*)(BAc + SXO(0)))[xb * 4 + xq] = x[(size_t)(bBase + xb) * TT * 4 + xq];

    float bias0[4][2], bias1[4][2], w0x[2][4][4];
    #pragma unroll
    for (int G = 0; G < 4; G++)
        #pragma unroll
        for (int uh = 0; uh < 2; uh++) {
            int j = G * 64 + u0 + uh * 8;
            bias0[G][uh] = bih0[j] + bhh0[j];
            bias1[G][uh] = bih1[j] + bhh1[j];
            #pragma unroll
            for (int q = 0; q < 4; q++) w0x[uh][G][q] = Wih0[j * 4 + q];
        }
    float c0s[2][2][2], c1s[2][2][2];
    #pragma unroll
    for (int i = 0; i < 2; i++)
        #pragma unroll
        for (int jj = 0; jj < 2; jj++)
            #pragma unroll
            for (int kk = 0; kk < 2; kk++) { c0s[i][jj][kk] = 0.f; c1s[i][jj][kk] = 0.f; }

    __syncthreads();

    // Wavefront: iter ts computes h0[ts] (ts<TT) and h1[ts-1] (ts>0).
    // Buffers at iter start (p = ts&1): h0T(p)=h0[ts-1], h1T(p)=h1[ts-2], sX(p)=x[ts].
    #pragma unroll 1
    for (int ts = 0; ts <= TT; ts++) {
        const int p = ts & 1;
        float xpre = 0.f;
        if (xok && ts + 1 < TT)
            xpre = x[((size_t)(bBase + xb) * TT + ts + 1) * 4 + xq];

        // ===== layer 1 (step ts-1): acc1 = Whh1*h1[ts-2] + Wih1*h0[ts-1] =====
        if (ts > 0) {
            float acc1[4][2][4];
            #pragma unroll
            for (int G = 0; G < 4; G++)
                #pragma unroll
                for (int nt = 0; nt < 2; nt++)
                    #pragma unroll
                    for (int c = 0; c < 4; c++) acc1[G][nt][c] = 0.f;
            gemm2(acc1, BAu + W1HF, BAu + H1T(p, 0), BAu + H1T(p, 1),
                  aRow, bRow, hbA, xorA, hbB, xorB);
            gemm2(acc1, BAu + W1IF, BAu + H0T(p, 0), BAu + H0T(p, 1),
                  aRow, bRow, hbA, xorA, hbB, xorB);

            #pragma unroll
            for (int nt = 0; nt < 2; nt++)
                #pragma unroll
                for (int ch = 0; ch < 2; ch++) {
                    const int b = nh * 16 + nt * 8 + 2 * t4 + ch;
                    #pragma unroll
                    for (int uh = 0; uh < 2; uh++) {
                        float pre[4];
                        #pragma unroll
                        for (int G = 0; G < 4; G++)
                            pre[G] = acc1[G][nt][uh * 2 + ch] + bias1[G][uh];
                        float gi = fsig(pre[0]), gf = fsig(pre[1]);
                        float gg = tanhapx(pre[2]), go = fsig(pre[3]);
                        float &c = c1s[nt][uh][ch];
                        c = gf * c + gi * gg;
                        float h = go * tanhapx(c);
                        const int u = u0 + uh * 8;
                        if (ts < TT) {
                            uint32_t off = ((uint32_t)(b * 128 + u * 2)) ^ ((uint32_t)(b & 7) << 4);
                            __half hh = __float2half_rn(h);
                            *(__half*)(BAc + H1T(p ^ 1, 0) + off) = hh;
                            *(__half*)(BAc + H1T(p ^ 1, 1) + off) =
                                __float2half_rn(h - __half2float(hh));
                        } else {
                            ((float*)(BAc + HS_OFF))[b * 64 + u] = h;  // final h1 fp32
                        }
                    }
                }
        }

        // ===== layer 0 (step ts): acc0 = Whh0*h0[ts-1]; act adds Wih0*x[ts] =====
        if (ts < TT) {
            float acc0[4][2][4];
            #pragma unroll
            for (int G = 0; G < 4; G++)
                #pragma unroll
                for (int nt = 0; nt < 2; nt++)
                    #pragma unroll
                    for (int c = 0; c < 4; c++) acc0[G][nt][c] = 0.f;
            gemm2(acc0, BAu + W0F, BAu + H0T(p, 0), BAu + H0T(p, 1),
                  aRow, bRow, hbA, xorA, hbB, xorB);

            #pragma unroll
            for (int nt = 0; nt < 2; nt++)
                #pragma unroll
                for (int ch = 0; ch < 2; ch++) {
                    const int b = nh * 16 + nt * 8 + 2 * t4 + ch;
                    const float4 xv = *(const float4*)(BAc + SXO(p) + b * 16);
                    #pragma unroll
                    for (int uh = 0; uh < 2; uh++) {
                        float pre[4];
                        #pragma unroll
                        for (int G = 0; G < 4; G++)
                            pre[G] = acc0[G][nt][uh * 2 + ch] + bias0[G][uh]
                                   + w0x[uh][G][0] * xv.x + w0x[uh][G][1] * xv.y
                                   + w0x[uh][G][2] * xv.z + w0x[uh][G][3] * xv.w;
                        float gi = fsig(pre[0]), gf = fsig(pre[1]);
                        float gg = tanhapx(pre[2]), go = fsig(pre[3]);
                        float &c = c0s[nt][uh][ch];
                        c = gf * c + gi * gg;
                        float h = go * tanhapx(c);
                        const int u = u0 + uh * 8;
                        uint32_t off = ((uint32_t)(b * 128 + u * 2)) ^ ((uint32_t)(b & 7) << 4);
                        __half hh = __float2half_rn(h);
                        *(__half*)(BAc + H0T(p ^ 1, 0) + off) = hh;
                        *(__half*)(BAc + H0T(p ^ 1, 1) + off) =
                            __float2half_rn(h - __half2float(hh));
                    }
                }
            if (t < 112) ((float*)(BAc + SXO(p ^ 1)))[xb * 4 + xq] = xpre;
        }

        __syncthreads();   // single barrier per iteration
    }

    // ================= MLP head =================
    const float* hs = (const float*)(BAc + HS_OFF);   // fp32 h1 final [32][64]
    float* W1s = (float*)(BAc + W1HF);                // W1^T in dead weight region
    for (int e = t; e < 64 * 64; e += THREADS) {
        int n = e >> 6, k = e & 63;
        W1s[k * 64 + n] = W1[e];
    }
    __syncthreads();

    const int u2 = t & 63, pid = t >> 6;
    float bb = b1[u2];
    float zv[7];
    #pragma unroll
    for (int b = 0; b < 7; b++) {
        int row = pid * 7 + b;
        float sum = bb;
        #pragma unroll 8
        for (int k = 0; k < 64; k++)
            sum += W1s[k * 64 + u2] * hs[row * 64 + k];
        zv[b] = fmaxf(sum, 0.f);
    }
    __syncthreads();
    float* sZ = (float*)(BAc + W0F);                  // dead region, [28][64] fp32
    #pragma unroll
    for (int b = 0; b < 7; b++) sZ[(pid * 7 + b) * 64 + u2] = zv[b];
    __syncthreads();

    for (int e = t; e < BT * 12; e += THREADS) {
        int b = e / 12, o = e % 12;
        if (bBase + b < BATCH) {
            float sum = __ldg(&b2[o]);
            #pragma unroll 8
            for (int n = 0; n < 64; n++)
                sum += __ldg(&W2[o * 64 + n]) * sZ[b * 64 + n];
            out[(size_t)(bBase + b) * 12 + o] = sum;
        }
    }
}

extern "C" void kernel_launch(void* const* d_in, const int* in_sizes, int n_in,
                              void* d_out, int out_size)
{
    (void)in_sizes; (void)n_in; (void)out_size;
    cudaFuncSetAttribute(weather_lstm_mma,
                         cudaFuncAttributeMaxDynamicSharedMemorySize, SMEM_BYTES);
    weather_lstm_mma<<<NGRID, THREADS, SMEM_BYTES>>>(
        (const float*)d_in[0],
        (const float*)d_in[1],  (const float*)d_in[2],
        (const float*)d_in[3],  (const float*)d_in[4],
        (const float*)d_in[5],  (const float*)d_in[6],
        (const float*)d_in[7],  (const float*)d_in[8],
        (const float*)d_in[9],  (const float*)d_in[10],
        (const float*)d_in[11], (const float*)d_in[12],
        (float*)d_out);
}

// round 11
// speedup vs baseline: 3.0909x; 1.0233x over previous
#include <cuda_runtime.h>
#include <cuda_fp16.h>
#include <cstdint>

#define THREADS 256
#define BT      28
#define BATCH   4096
#define TT      168
#define NGRID   147

// smem byte offsets from 1024-aligned base
#define W0F    0u        // Whh0 fp16 : [256 rows][128B] SW128 (64 cols fp16)
#define W1HF   32768u    // Whh1
#define W1IF   65536u    // Wih1
#define H0T(p,s)  (98304u  + ((p)*2u+(s))*4096u)   // h0 tiles [32][64] fp16 (s: hi/lo)
#define H1T(p,s)  (114688u + ((p)*2u+(s))*4096u)
#define SXO(p)    (131072u + (p)*512u)             // x fp32 [32][4] ping-pong
#define HS_OFF    132096u                          // fp32 h1 staging [32][64] — DEDICATED
#define SMEM_BYTES 141312                          // 132096+8192+1024 align pad

__device__ __forceinline__ uint32_t smem_u32(const void* p) {
    uint32_t a;
    asm("{ .reg .u64 t; cvta.to.shared.u64 t, %1; cvt.u32.u64 %0, t; }" : "=r"(a) : "l"(p));
    return a;
}
__device__ __forceinline__ float tanhapx(float x) {
    float y; asm("tanh.approx.f32 %0, %1;" : "=f"(y) : "f"(x)); return y;
}
__device__ __forceinline__ float fsig(float x) { return fmaf(0.5f, tanhapx(0.5f * x), 0.5f); }

__device__ __forceinline__ void ldsm4(uint32_t &r0, uint32_t &r1, uint32_t &r2, uint32_t &r3, uint32_t a) {
    asm volatile("ldmatrix.sync.aligned.m8n8.x4.shared.b16 {%0,%1,%2,%3}, [%4];"
                 : "=r"(r0), "=r"(r1), "=r"(r2), "=r"(r3) : "r"(a));
}
__device__ __forceinline__ void ldsm2(uint32_t &r0, uint32_t &r1, uint32_t a) {
    asm volatile("ldmatrix.sync.aligned.m8n8.x2.shared.b16 {%0,%1}, [%2];"
                 : "=r"(r0), "=r"(r1) : "r"(a));
}
__device__ __forceinline__ void mma_f16(float &c0, float &c1, float &c2, float &c3,
                                        uint32_t a0, uint32_t a1, uint32_t a2, uint32_t a3,
                                        uint32_t b0, uint32_t b1) {
    asm volatile("mma.sync.aligned.m16n8k16.row.col.f32.f16.f16.f32 "
                 "{%0,%1,%2,%3}, {%4,%5,%6,%7}, {%8,%9}, {%0,%1,%2,%3};"
                 : "+f"(c0), "+f"(c1), "+f"(c2), "+f"(c3)
                 : "r"(a0), "r"(a1), "r"(a2), "r"(a3), "r"(b0), "r"(b1));
}

// fp16 2-term GEMM accumulate over K=64 (4 k16 chunks): acc += A*(Bhi + Blo)
__device__ __forceinline__ void gemm2(float acc[4][2][4],
                                      uint32_t AB,
                                      uint32_t BhiB, uint32_t BloB,
                                      const uint32_t* aRow, const uint32_t* bRow,
                                      uint32_t hbA, uint32_t xorA,
                                      uint32_t hbB, uint32_t xorB)
{
    #pragma unroll
    for (int kc = 0; kc < 4; kc++) {
        const uint32_t kA = ((uint32_t)(kc * 32) + hbA) ^ xorA;
        const uint32_t kB = ((uint32_t)(kc * 32) + hbB) ^ xorB;
        uint32_t ah[4][4], bh[2][2], bl[2][2];
        #pragma unroll
        for (int G = 0; G < 4; G++)
            ldsm4(ah[G][0], ah[G][1], ah[G][2], ah[G][3], AB + aRow[G] + kA);
        #pragma unroll
        for (int nt = 0; nt < 2; nt++) {
            ldsm2(bh[nt][0], bh[nt][1], BhiB + bRow[nt] + kB);
            ldsm2(bl[nt][0], bl[nt][1], BloB + bRow[nt] + kB);
        }
        #pragma unroll
        for (int G = 0; G < 4; G++)
            #pragma unroll
            for (int nt = 0; nt < 2; nt++) {
                mma_f16(acc[G][nt][0], acc[G][nt][1], acc[G][nt][2], acc[G][nt][3],
                        ah[G][0], ah[G][1], ah[G][2], ah[G][3], bh[nt][0], bh[nt][1]);
                mma_f16(acc[G][nt][0], acc[G][nt][1], acc[G][nt][2], acc[G][nt][3],
                        ah[G][0], ah[G][1], ah[G][2], ah[G][3], bl[nt][0], bl[nt][1]);
            }
    }
}

extern "C" __global__ void __launch_bounds__(THREADS, 1)
weather_lstm_mma(const float* __restrict__ x,
                 const float* __restrict__ Wih0, const float* __restrict__ Whh0,
                 const float* __restrict__ bih0, const float* __restrict__ bhh0,
                 const float* __restrict__ Wih1, const float* __restrict__ Whh1,
                 const float* __restrict__ bih1, const float* __restrict__ bhh1,
                 const float* __restrict__ W1,  const float* __restrict__ b1,
                 const float* __restrict__ W2,  const float* __restrict__ b2,
                 float* __restrict__ out)
{
    extern __shared__ char smraw[];
    const uint32_t raw = smem_u32(smraw);
    const uint32_t BAu = (raw + 1023u) & ~1023u;
    char* BAc = smraw + (BAu - raw);

    const int t    = threadIdx.x;
    const int w    = t >> 5, lane = t & 31;
    const int m    = w >> 1, nh = w & 1;       // group = nh (batch-half); warps interleave SMSPs
    const int g4   = lane >> 2, t4 = lane & 3;
    const int u0   = m * 16 + g4;
    const int bBase = blockIdx.x * BT;
    const int barid = 1 + nh;                  // named barrier per group (128 threads)

    const int      rlA  = (lane & 7) + ((lane >> 3) & 1) * 8;
    const uint32_t hbA  = (uint32_t)(((lane >> 4) & 1) * 16);
    const uint32_t xorA = (uint32_t)((lane & 7) << 4);
    const int      laneB = lane & 15;
    const int      rlB  = laneB & 7;
    const uint32_t hbB  = (uint32_t)(((laneB >> 3) & 1) * 16);
    const uint32_t xorB = (uint32_t)((laneB & 7) << 4);

    uint32_t aRow[4], bRow[2];
    #pragma unroll
    for (int G = 0; G < 4; G++) aRow[G] = (uint32_t)((G * 64 + m * 16 + rlA) * 128);
    #pragma unroll
    for (int nt = 0; nt < 2; nt++) bRow[nt] = (uint32_t)((nh * 16 + nt * 8 + rlB) * 128);

    // ---- preload weights: fp32 -> fp16 rounded, SW128 [256][64] ----
    for (int e = t; e < 256 * 64; e += THREADS) {
        int j = e >> 6, k = e & 63;
        uint32_t off = ((uint32_t)(j * 128 + k * 2)) ^ ((uint32_t)(j & 7) << 4);
        *(__half*)(BAc + W0F  + off) = __float2half_rn(Whh0[e]);
        *(__half*)(BAc + W1HF + off) = __float2half_rn(Whh1[e]);
        *(__half*)(BAc + W1IF + off) = __float2half_rn(Wih1[e]);
    }
    for (int e = t; e < 8192; e += THREADS) ((uint32_t*)(BAc + H0T(0, 0)))[e] = 0u;
    for (int e = t; e < 256;  e += THREADS) ((float*)(BAc + SXO(0)))[e] = 0.f;

    // group-local x duty: group nh loads x for its own batches nh*16 + 0..(nh?11:15)
    const int gl   = m * 32 + lane;            // 0..127 within group
    const int xbl  = gl >> 2, xq = gl & 3;
    const int xb   = nh * 16 + xbl;
    const bool xduty = xbl < (nh ? 12 : 16);   // BT=28: group0 16 batches, group1 12
    const bool xok   = xduty && (bBase + xb < BATCH);
    if (xok) ((float*)(BAc + SXO(0)))[xb * 4 + xq] = x[(size_t)(bBase + xb) * TT * 4 + xq];

    float bias0[4][2], bias1[4][2], w0x[2][4][4];
    #pragma unroll
    for (int G = 0; G < 4; G++)
        #pragma unroll
        for (int uh = 0; uh < 2; uh++) {
            int j = G * 64 + u0 + uh * 8;
            bias0[G][uh] = bih0[j] + bhh0[j];
            bias1[G][uh] = bih1[j] + bhh1[j];
            #pragma unroll
            for (int q = 0; q < 4; q++) w0x[uh][G][q] = Wih0[j * 4 + q];
        }
    float c0s[2][2][2], c1s[2][2][2];
    #pragma unroll
    for (int i = 0; i < 2; i++)
        #pragma unroll
        for (int jj = 0; jj < 2; jj++)
            #pragma unroll
            for (int kk = 0; kk < 2; kk++) { c0s[i][jj][kk] = 0.f; c1s[i][jj][kk] = 0.f; }

    __syncthreads();   // weights + zeroed state visible CTA-wide

    // Wavefront, per-group pipeline: iter ts computes h0[ts] (ts<TT) and h1[ts-1] (ts>0).
    // All in-loop smem traffic is group-private (batch rows nh*16..) except read-only
    // weights; HS is a dedicated region (no aliasing with live tiles) so free group
    // drift is safe.
    #pragma unroll 1
    for (int ts = 0; ts <= TT; ts++) {
        const int p = ts & 1;
        float xpre = 0.f;
        if (xok && ts + 1 < TT)
            xpre = x[((size_t)(bBase + xb) * TT + ts + 1) * 4 + xq];

        // ===== layer 1 (step ts-1): acc1 = Whh1*h1[ts-2] + Wih1*h0[ts-1] =====
        if (ts > 0) {
            float acc1[4][2][4];
            #pragma unroll
            for (int G = 0; G < 4; G++)
                #pragma unroll
                for (int nt = 0; nt < 2; nt++)
                    #pragma unroll
                    for (int c = 0; c < 4; c++) acc1[G][nt][c] = 0.f;
            gemm2(acc1, BAu + W1HF, BAu + H1T(p, 0), BAu + H1T(p, 1),
                  aRow, bRow, hbA, xorA, hbB, xorB);
            gemm2(acc1, BAu + W1IF, BAu + H0T(p, 0), BAu + H0T(p, 1),
                  aRow, bRow, hbA, xorA, hbB, xorB);

            #pragma unroll
            for (int nt = 0; nt < 2; nt++)
                #pragma unroll
                for (int ch = 0; ch < 2; ch++) {
                    const int b = nh * 16 + nt * 8 + 2 * t4 + ch;
                    #pragma unroll
                    for (int uh = 0; uh < 2; uh++) {
                        float pre[4];
                        #pragma unroll
                        for (int G = 0; G < 4; G++)
                            pre[G] = acc1[G][nt][uh * 2 + ch] + bias1[G][uh];
                        float gi = fsig(pre[0]), gf = fsig(pre[1]);
                        float gg = tanhapx(pre[2]), go = fsig(pre[3]);
                        float &c = c1s[nt][uh][ch];
                        c = gf * c + gi * gg;
                        float h = go * tanhapx(c);
                        const int u = u0 + uh * 8;
                        if (ts < TT) {
                            uint32_t off = ((uint32_t)(b * 128 + u * 2)) ^ ((uint32_t)(b & 7) << 4);
                            __half hh = __float2half_rn(h);
                            *(__half*)(BAc + H1T(p ^ 1, 0) + off) = hh;
                            *(__half*)(BAc + H1T(p ^ 1, 1) + off) =
                                __float2half_rn(h - __half2float(hh));
                        } else {
                            ((float*)(BAc + HS_OFF))[b * 64 + u] = h;  // final h1, dedicated
                        }
                    }
                }
        }

        // ===== layer 0 (step ts): acc0 = Whh0*h0[ts-1]; act adds Wih0*x[ts] =====
        if (ts < TT) {
            float acc0[4][2][4];
            #pragma unroll
            for (int G = 0; G < 4; G++)
                #pragma unroll
                for (int nt = 0; nt < 2; nt++)
                    #pragma unroll
                    for (int c = 0; c < 4; c++) acc0[G][nt][c] = 0.f;
            gemm2(acc0, BAu + W0F, BAu + H0T(p, 0), BAu + H0T(p, 1),
                  aRow, bRow, hbA, xorA, hbB, xorB);

            #pragma unroll
            for (int nt = 0; nt < 2; nt++)
                #pragma unroll
                for (int ch = 0; ch < 2; ch++) {
                    const int b = nh * 16 + nt * 8 + 2 * t4 + ch;
                    const float4 xv = *(const float4*)(BAc + SXO(p) + b * 16);
                    #pragma unroll
                    for (int uh = 0; uh < 2; uh++) {
                        float pre[4];
                        #pragma unroll
                        for (int G = 0; G < 4; G++)
                            pre[G] = acc0[G][nt][uh * 2 + ch] + bias0[G][uh]
                                   + w0x[uh][G][0] * xv.x + w0x[uh][G][1] * xv.y
                                   + w0x[uh][G][2] * xv.z + w0x[uh][G][3] * xv.w;
                        float gi = fsig(pre[0]), gf = fsig(pre[1]);
                        float gg = tanhapx(pre[2]), go = fsig(pre[3]);
                        float &c = c0s[nt][uh][ch];
                        c = gf * c + gi * gg;
                        float h = go * tanhapx(c);
                        const int u = u0 + uh * 8;
                        uint32_t off = ((uint32_t)(b * 128 + u * 2)) ^ ((uint32_t)(b & 7) << 4);
                        __half hh = __float2half_rn(h);
                        *(__half*)(BAc + H0T(p ^ 1, 0) + off) = hh;
                        *(__half*)(BAc + H0T(p ^ 1, 1) + off) =
                            __float2half_rn(h - __half2float(hh));
                    }
                }
            if (xduty) ((float*)(BAc + SXO(p ^ 1)))[xb * 4 + xq] = xpre;
        }

        asm volatile("bar.sync %0, 128;" :: "r"(barid) : "memory");  // group-scoped
    }

    __syncthreads();   // re-join groups before reusing weight regions

    // ================= MLP head =================
    const float* hs = (const float*)(BAc + HS_OFF);   // fp32 h1 final [32][64]
    float* W1s = (float*)(BAc + W1HF);                // W1^T in dead weight region
    for (int e = t; e < 64 * 64; e += THREADS) {
        int n = e >> 6, k = e & 63;
        W1s[k * 64 + n] = W1[e];
    }
    __syncthreads();

    const int u2 = t & 63, pid = t >> 6;
    float bb = b1[u2];
    float zv[7];
    #pragma unroll
    for (int b = 0; b < 7; b++) {
        int row = pid * 7 + b;
        float sum = bb;
        #pragma unroll 8
        for (int k = 0; k < 64; k++)
            sum += W1s[k * 64 + u2] * hs[row * 64 + k];
        zv[b] = fmaxf(sum, 0.f);
    }
    __syncthreads();
    float* sZ = (float*)(BAc + W0F);                  // dead region, [28][64] fp32
    #pragma unroll
    for (int b = 0; b < 7; b++) sZ[(pid * 7 + b) * 64 + u2] = zv[b];
    __syncthreads();

    for (int e = t; e < BT * 12; e += THREADS) {
        int b = e / 12, o = e % 12;
        if (bBase + b < BATCH) {
            float sum = __ldg(&b2[o]);
            #pragma unroll 8
            for (int n = 0; n < 64; n++)
                sum += __ldg(&W2[o * 64 + n]) * sZ[b * 64 + n];
            out[(size_t)(bBase + b) * 12 + o] = sum;
        }
    }
}

extern "C" void kernel_launch(void* const* d_in, const int* in_sizes, int n_in,
                              void* d_out, int out_size)
{
    (void)in_sizes; (void)n_in; (void)out_size;
    cudaFuncSetAttribute(weather_lstm_mma,
                         cudaFuncAttributeMaxDynamicSharedMemorySize, SMEM_BYTES);
    weather_lstm_mma<<<NGRID, THREADS, SMEM_BYTES>>>(
        (const float*)d_in[0],
        (const float*)d_in[1],  (const float*)d_in[2],
        (const float*)d_in[3],  (const float*)d_in[4],
        (const float*)d_in[5],  (const float*)d_in[6],
        (const float*)d_in[7],  (const float*)d_in[8],
        (const float*)d_in[9],  (const float*)d_in[10],
        (const float*)d_in[11], (const float*)d_in[12],
        (float*)d_out);
}

// round 12
// speedup vs baseline: 4.1919x; 1.3562x over previous
#include <cuda_runtime.h>
#include <cuda_fp16.h>
#include <cstdint>

#define THREADS 256
#define BT      28
#define BATCH   4096
#define TT      168
#define NGRID   147

// smem byte offsets from 1024-aligned base
#define W0F    0u        // Whh0 fp16 : [256 rows][128B] SW128 (64 cols fp16)
#define W1HF   32768u    // Whh1
#define W1IF   65536u    // Wih1
#define H0T(p)    (98304u  + (p)*4096u)   // h0 tile [32][64] fp16, ping-pong
#define H1T(p)    (106496u + (p)*4096u)   // h1 tile
#define SXO(p)    (114688u + (p)*512u)    // x fp32 [32][4] ping-pong
#define HS_OFF    115712u                 // fp32 h1 staging [32][64] — dedicated
#define SMEM_BYTES 124928

__device__ __forceinline__ uint32_t smem_u32(const void* p) {
    uint32_t a;
    asm("{ .reg .u64 t; cvta.to.shared.u64 t, %1; cvt.u32.u64 %0, t; }" : "=r"(a) : "l"(p));
    return a;
}
__device__ __forceinline__ float tanhapx(float x) {
    float y; asm("tanh.approx.f32 %0, %1;" : "=f"(y) : "f"(x)); return y;
}
__device__ __forceinline__ float fsig(float x) { return fmaf(0.5f, tanhapx(0.5f * x), 0.5f); }

__device__ __forceinline__ void ldsm4(uint32_t &r0, uint32_t &r1, uint32_t &r2, uint32_t &r3, uint32_t a) {
    asm volatile("ldmatrix.sync.aligned.m8n8.x4.shared.b16 {%0,%1,%2,%3}, [%4];"
                 : "=r"(r0), "=r"(r1), "=r"(r2), "=r"(r3) : "r"(a));
}
__device__ __forceinline__ void ldsm2(uint32_t &r0, uint32_t &r1, uint32_t a) {
    asm volatile("ldmatrix.sync.aligned.m8n8.x2.shared.b16 {%0,%1}, [%2];"
                 : "=r"(r0), "=r"(r1) : "r"(a));
}
__device__ __forceinline__ void mma_f16(float &c0, float &c1, float &c2, float &c3,
                                        uint32_t a0, uint32_t a1, uint32_t a2, uint32_t a3,
                                        uint32_t b0, uint32_t b1) {
    asm volatile("mma.sync.aligned.m16n8k16.row.col.f32.f16.f16.f32 "
                 "{%0,%1,%2,%3}, {%4,%5,%6,%7}, {%8,%9}, {%0,%1,%2,%3};"
                 : "+f"(c0), "+f"(c1), "+f"(c2), "+f"(c3)
                 : "r"(a0), "r"(a1), "r"(a2), "r"(a3), "r"(b0), "r"(b1));
}

// single-term fp16 GEMM accumulate over K=64 (4 k16 chunks): acc += A*B
__device__ __forceinline__ void gemm1(float acc[4][2][4],
                                      uint32_t AB, uint32_t BB,
                                      const uint32_t* aRow, const uint32_t* bRow,
                                      uint32_t hbA, uint32_t xorA,
                                      uint32_t hbB, uint32_t xorB)
{
    #pragma unroll
    for (int kc = 0; kc < 4; kc++) {
        const uint32_t kA = ((uint32_t)(kc * 32) + hbA) ^ xorA;
        const uint32_t kB = ((uint32_t)(kc * 32) + hbB) ^ xorB;
        uint32_t ah[4][4], bh[2][2];
        #pragma unroll
        for (int G = 0; G < 4; G++)
            ldsm4(ah[G][0], ah[G][1], ah[G][2], ah[G][3], AB + aRow[G] + kA);
        #pragma unroll
        for (int nt = 0; nt < 2; nt++)
            ldsm2(bh[nt][0], bh[nt][1], BB + bRow[nt] + kB);
        #pragma unroll
        for (int G = 0; G < 4; G++)
            #pragma unroll
            for (int nt = 0; nt < 2; nt++)
                mma_f16(acc[G][nt][0], acc[G][nt][1], acc[G][nt][2], acc[G][nt][3],
                        ah[G][0], ah[G][1], ah[G][2], ah[G][3], bh[nt][0], bh[nt][1]);
    }
}

extern "C" __global__ void __launch_bounds__(THREADS, 1)
weather_lstm_mma(const float* __restrict__ x,
                 const float* __restrict__ Wih0, const float* __restrict__ Whh0,
                 const float* __restrict__ bih0, const float* __restrict__ bhh0,
                 const float* __restrict__ Wih1, const float* __restrict__ Whh1,
                 const float* __restrict__ bih1, const float* __restrict__ bhh1,
                 const float* __restrict__ W1,  const float* __restrict__ b1,
                 const float* __restrict__ W2,  const float* __restrict__ b2,
                 float* __restrict__ out)
{
    extern __shared__ char smraw[];
    const uint32_t raw = smem_u32(smraw);
    const uint32_t BAu = (raw + 1023u) & ~1023u;
    char* BAc = smraw + (BAu - raw);

    const int t    = threadIdx.x;
    const int w    = t >> 5, lane = t & 31;
    const int m    = w >> 1, nh = w & 1;       // group = nh (batch-half)
    const int g4   = lane >> 2, t4 = lane & 3;
    const int u0   = m * 16 + g4;
    const int bBase = blockIdx.x * BT;
    const int barid = 1 + nh;                  // named barrier per group (128 threads)

    const int      rlA  = (lane & 7) + ((lane >> 3) & 1) * 8;
    const uint32_t hbA  = (uint32_t)(((lane >> 4) & 1) * 16);
    const uint32_t xorA = (uint32_t)((lane & 7) << 4);
    const int      laneB = lane & 15;
    const int      rlB  = laneB & 7;
    const uint32_t hbB  = (uint32_t)(((laneB >> 3) & 1) * 16);
    const uint32_t xorB = (uint32_t)((laneB & 7) << 4);

    uint32_t aRow[4], bRow[2];
    #pragma unroll
    for (int G = 0; G < 4; G++) aRow[G] = (uint32_t)((G * 64 + m * 16 + rlA) * 128);
    #pragma unroll
    for (int nt = 0; nt < 2; nt++) bRow[nt] = (uint32_t)((nh * 16 + nt * 8 + rlB) * 128);

    // ---- preload weights: fp32 -> fp16 rounded, SW128 [256][64] ----
    for (int e = t; e < 256 * 64; e += THREADS) {
        int j = e >> 6, k = e & 63;
        uint32_t off = ((uint32_t)(j * 128 + k * 2)) ^ ((uint32_t)(j & 7) << 4);
        *(__half*)(BAc + W0F  + off) = __float2half_rn(Whh0[e]);
        *(__half*)(BAc + W1HF + off) = __float2half_rn(Whh1[e]);
        *(__half*)(BAc + W1IF + off) = __float2half_rn(Wih1[e]);
    }
    for (int e = t; e < 4096; e += THREADS) ((uint32_t*)(BAc + H0T(0)))[e] = 0u;  // all 4 h tiles
    for (int e = t; e < 256;  e += THREADS) ((float*)(BAc + SXO(0)))[e] = 0.f;

    // group-local x duty
    const int gl   = m * 32 + lane;            // 0..127 within group
    const int xbl  = gl >> 2, xq = gl & 3;
    const int xb   = nh * 16 + xbl;
    const bool xduty = xbl < (nh ? 12 : 16);   // BT=28: group0 16 batches, group1 12
    const bool xok   = xduty && (bBase + xb < BATCH);
    if (xok) ((float*)(BAc + SXO(0)))[xb * 4 + xq] = x[(size_t)(bBase + xb) * TT * 4 + xq];

    float bias0[4][2], bias1[4][2], w0x[2][4][4];
    #pragma unroll
    for (int G = 0; G < 4; G++)
        #pragma unroll
        for (int uh = 0; uh < 2; uh++) {
            int j = G * 64 + u0 + uh * 8;
            bias0[G][uh] = bih0[j] + bhh0[j];
            bias1[G][uh] = bih1[j] + bhh1[j];
            #pragma unroll
            for (int q = 0; q < 4; q++) w0x[uh][G][q] = Wih0[j * 4 + q];
        }
    float c0s[2][2][2], c1s[2][2][2];
    #pragma unroll
    for (int i = 0; i < 2; i++)
        #pragma unroll
        for (int jj = 0; jj < 2; jj++)
            #pragma unroll
            for (int kk = 0; kk < 2; kk++) { c0s[i][jj][kk] = 0.f; c1s[i][jj][kk] = 0.f; }

    __syncthreads();   // weights + zeroed state visible CTA-wide

    // Wavefront: iter ts computes h0[ts] (ts<TT) and h1[ts-1] (ts>0).
    #pragma unroll 1
    for (int ts = 0; ts <= TT; ts++) {
        const int p = ts & 1;
        float xpre = 0.f;
        if (xok && ts + 1 < TT)
            xpre = x[((size_t)(bBase + xb) * TT + ts + 1) * 4 + xq];

        // ===== layer 1 (step ts-1): acc1 = Whh1*h1[ts-2] + Wih1*h0[ts-1] =====
        if (ts > 0) {
            float acc1[4][2][4];
            #pragma unroll
            for (int G = 0; G < 4; G++)
                #pragma unroll
                for (int nt = 0; nt < 2; nt++)
                    #pragma unroll
                    for (int c = 0; c < 4; c++) acc1[G][nt][c] = 0.f;
            gemm1(acc1, BAu + W1HF, BAu + H1T(p), aRow, bRow, hbA, xorA, hbB, xorB);
            gemm1(acc1, BAu + W1IF, BAu + H0T(p), aRow, bRow, hbA, xorA, hbB, xorB);

            #pragma unroll
            for (int nt = 0; nt < 2; nt++)
                #pragma unroll
                for (int ch = 0; ch < 2; ch++) {
                    const int b = nh * 16 + nt * 8 + 2 * t4 + ch;
                    #pragma unroll
                    for (int uh = 0; uh < 2; uh++) {
                        float pre[4];
                        #pragma unroll
                        for (int G = 0; G < 4; G++)
                            pre[G] = acc1[G][nt][uh * 2 + ch] + bias1[G][uh];
                        float gi = fsig(pre[0]), gf = fsig(pre[1]);
                        float gg = tanhapx(pre[2]), go = fsig(pre[3]);
                        float &c = c1s[nt][uh][ch];
                        c = gf * c + gi * gg;
                        float h = go * tanhapx(c);
                        const int u = u0 + uh * 8;
                        if (ts < TT) {
                            uint32_t off = ((uint32_t)(b * 128 + u * 2)) ^ ((uint32_t)(b & 7) << 4);
                            *(__half*)(BAc + H1T(p ^ 1) + off) = __float2half_rn(h);
                        } else {
                            ((float*)(BAc + HS_OFF))[b * 64 + u] = h;  // final h1 fp32
                        }
                    }
                }
        }

        // ===== layer 0 (step ts): acc0 = Whh0*h0[ts-1]; act adds Wih0*x[ts] =====
        if (ts < TT) {
            float acc0[4][2][4];
            #pragma unroll
            for (int G = 0; G < 4; G++)
                #pragma unroll
                for (int nt = 0; nt < 2; nt++)
                    #pragma unroll
                    for (int c = 0; c < 4; c++) acc0[G][nt][c] = 0.f;
            gemm1(acc0, BAu + W0F, BAu + H0T(p), aRow, bRow, hbA, xorA, hbB, xorB);

            #pragma unroll
            for (int nt = 0; nt < 2; nt++)
                #pragma unroll
                for (int ch = 0; ch < 2; ch++) {
                    const int b = nh * 16 + nt * 8 + 2 * t4 + ch;
                    const float4 xv = *(const float4*)(BAc + SXO(p) + b * 16);
                    #pragma unroll
                    for (int uh = 0; uh < 2; uh++) {
                        float pre[4];
                        #pragma unroll
                        for (int G = 0; G < 4; G++)
                            pre[G] = acc0[G][nt][uh * 2 + ch] + bias0[G][uh]
                                   + w0x[uh][G][0] * xv.x + w0x[uh][G][1] * xv.y
                                   + w0x[uh][G][2] * xv.z + w0x[uh][G][3] * xv.w;
                        float gi = fsig(pre[0]), gf = fsig(pre[1]);
                        float gg = tanhapx(pre[2]), go = fsig(pre[3]);
                        float &c = c0s[nt][uh][ch];
                        c = gf * c + gi * gg;
                        float h = go * tanhapx(c);
                        const int u = u0 + uh * 8;
                        uint32_t off = ((uint32_t)(b * 128 + u * 2)) ^ ((uint32_t)(b & 7) << 4);
                        *(__half*)(BAc + H0T(p ^ 1) + off) = __float2half_rn(h);
                    }
                }
            if (xduty) ((float*)(BAc + SXO(p ^ 1)))[xb * 4 + xq] = xpre;
        }

        asm volatile("bar.sync %0, 128;" :: "r"(barid) : "memory");  // group-scoped
    }

    __syncthreads();   // re-join groups before reusing weight regions

    // ================= MLP head =================
    const float* hs = (const float*)(BAc + HS_OFF);   // fp32 h1 final [32][64]
    float* W1s = (float*)(BAc + W1HF);                // W1^T in dead weight region
    for (int e = t; e < 64 * 64; e += THREADS) {
        int n = e >> 6, k = e & 63;
        W1s[k * 64 + n] = W1[e];
    }
    __syncthreads();

    const int u2 = t & 63, pid = t >> 6;
    float bb = b1[u2];
    float zv[7];
    #pragma unroll
    for (int b = 0; b < 7; b++) {
        int row = pid * 7 + b;
        float sum = bb;
        #pragma unroll 8
        for (int k = 0; k < 64; k++)
            sum += W1s[k * 64 + u2] * hs[row * 64 + k];
        zv[b] = fmaxf(sum, 0.f);
    }
    __syncthreads();
    float* sZ = (float*)(BAc + W0F);                  // dead region, [28][64] fp32
    #pragma unroll
    for (int b = 0; b < 7; b++) sZ[(pid * 7 + b) * 64 + u2] = zv[b];
    __syncthreads();

    for (int e = t; e < BT * 12; e += THREADS) {
        int b = e / 12, o = e % 12;
        if (bBase + b < BATCH) {
            float sum = __ldg(&b2[o]);
            #pragma unroll 8
            for (int n = 0; n < 64; n++)
                sum += __ldg(&W2[o * 64 + n]) * sZ[b * 64 + n];
            out[(size_t)(bBase + b) * 12 + o] = sum;
        }
    }
}

extern "C" void kernel_launch(void* const* d_in, const int* in_sizes, int n_in,
                              void* d_out, int out_size)
{
    (void)in_sizes; (void)n_in; (void)out_size;
    cudaFuncSetAttribute(weather_lstm_mma,
                         cudaFuncAttributeMaxDynamicSharedMemorySize, SMEM_BYTES);
    weather_lstm_mma<<<NGRID, THREADS, SMEM_BYTES>>>(
        (const float*)d_in[0],
        (const float*)d_in[1],  (const float*)d_in[2],
        (const float*)d_in[3],  (const float*)d_in[4],
        (const float*)d_in[5],  (const float*)d_in[6],
        (const float*)d_in[7],  (const float*)d_in[8],
        (const float*)d_in[9],  (const float*)d_in[10],
        (const float*)d_in[11], (const float*)d_in[12],
        (float*)d_out);
}

// round 13
// speedup vs baseline: 4.2937x; 1.0243x over previous
#include <cuda_runtime.h>
#include <cuda_fp16.h>
#include <cstdint>

#define THREADS 256
#define BT      28
#define BATCH   4096
#define TT      168
#define NGRID   147

// smem byte offsets from 1024-aligned base
#define W0F    0u        // Whh0 fp16 : [256 rows][128B] SW128 (64 cols fp16)
#define W1HF   32768u    // Whh1
#define W1IF   65536u    // Wih1
#define H0T(p)    (98304u  + (p)*4096u)   // h0 tile [32][64] fp16, ping-pong
#define H1T(p)    (106496u + (p)*4096u)   // h1 tile
#define SXO(p)    (114688u + (p)*512u)    // x fp32 [32][4] ping-pong
#define HS_OFF    115712u                 // fp32 h1 staging [32][64] — dedicated
#define SMEM_BYTES 124928

__device__ __forceinline__ uint32_t smem_u32(const void* p) {
    uint32_t a;
    asm("{ .reg .u64 t; cvta.to.shared.u64 t, %1; cvt.u32.u64 %0, t; }" : "=r"(a) : "l"(p));
    return a;
}
__device__ __forceinline__ float tanhapx(float x) {
    float y; asm("tanh.approx.f32 %0, %1;" : "=f"(y) : "f"(x)); return y;
}
__device__ __forceinline__ float fsig(float x) { return fmaf(0.5f, tanhapx(0.5f * x), 0.5f); }

__device__ __forceinline__ void ldsm4(uint32_t &r0, uint32_t &r1, uint32_t &r2, uint32_t &r3, uint32_t a) {
    asm volatile("ldmatrix.sync.aligned.m8n8.x4.shared.b16 {%0,%1,%2,%3}, [%4];"
                 : "=r"(r0), "=r"(r1), "=r"(r2), "=r"(r3) : "r"(a));
}
__device__ __forceinline__ void ldsm2(uint32_t &r0, uint32_t &r1, uint32_t a) {
    asm volatile("ldmatrix.sync.aligned.m8n8.x2.shared.b16 {%0,%1}, [%2];"
                 : "=r"(r0), "=r"(r1) : "r"(a));
}
__device__ __forceinline__ void mma_f16(float &c0, float &c1, float &c2, float &c3,
                                        uint32_t a0, uint32_t a1, uint32_t a2, uint32_t a3,
                                        uint32_t b0, uint32_t b1) {
    asm volatile("mma.sync.aligned.m16n8k16.row.col.f32.f16.f16.f32 "
                 "{%0,%1,%2,%3}, {%4,%5,%6,%7}, {%8,%9}, {%0,%1,%2,%3};"
                 : "+f"(c0), "+f"(c1), "+f"(c2), "+f"(c3)
                 : "r"(a0), "r"(a1), "r"(a2), "r"(a3), "r"(b0), "r"(b1));
}

// D[batch, gate-unit] GEMM: A = h tile (2 M-tiles of batches), B = weight (4 gate N-tiles).
// acc[mb][G][4] += h * W^T over K=64 (4 k16 chunks), B loaded from smem.
__device__ __forceinline__ void gemm_hw(float acc[2][4][4], uint32_t Ah, uint32_t Bw,
                                        const uint32_t* aRow, const uint32_t* bRowW,
                                        uint32_t hbA, uint32_t xorA,
                                        uint32_t hbB, uint32_t xorB)
{
    #pragma unroll
    for (int kc = 0; kc < 4; kc++) {
        const uint32_t kA = ((uint32_t)(kc * 32) + hbA) ^ xorA;
        const uint32_t kB = ((uint32_t)(kc * 32) + hbB) ^ xorB;
        uint32_t a[2][4], b[4][2];
        #pragma unroll
        for (int mb = 0; mb < 2; mb++)
            ldsm4(a[mb][0], a[mb][1], a[mb][2], a[mb][3], Ah + aRow[mb] + kA);
        #pragma unroll
        for (int G = 0; G < 4; G++)
            ldsm2(b[G][0], b[G][1], Bw + bRowW[G] + kB);
        #pragma unroll
        for (int mb = 0; mb < 2; mb++)
            #pragma unroll
            for (int G = 0; G < 4; G++)
                mma_f16(acc[mb][G][0], acc[mb][G][1], acc[mb][G][2], acc[mb][G][3],
                        a[mb][0], a[mb][1], a[mb][2], a[mb][3], b[G][0], b[G][1]);
    }
}

// Same but with register-resident B fragments (bw[kc][G][2]).
__device__ __forceinline__ void gemm_hres(float acc[2][4][4], uint32_t Ah,
                                          const uint32_t bw[4][4][2],
                                          const uint32_t* aRow,
                                          uint32_t hbA, uint32_t xorA)
{
    #pragma unroll
    for (int kc = 0; kc < 4; kc++) {
        const uint32_t kA = ((uint32_t)(kc * 32) + hbA) ^ xorA;
        uint32_t a[2][4];
        #pragma unroll
        for (int mb = 0; mb < 2; mb++)
            ldsm4(a[mb][0], a[mb][1], a[mb][2], a[mb][3], Ah + aRow[mb] + kA);
        #pragma unroll
        for (int mb = 0; mb < 2; mb++)
            #pragma unroll
            for (int G = 0; G < 4; G++)
                mma_f16(acc[mb][G][0], acc[mb][G][1], acc[mb][G][2], acc[mb][G][3],
                        a[mb][0], a[mb][1], a[mb][2], a[mb][3], bw[kc][G][0], bw[kc][G][1]);
    }
}

extern "C" __global__ void __launch_bounds__(THREADS, 1)
weather_lstm_mma(const float* __restrict__ x,
                 const float* __restrict__ Wih0, const float* __restrict__ Whh0,
                 const float* __restrict__ bih0, const float* __restrict__ bhh0,
                 const float* __restrict__ Wih1, const float* __restrict__ Whh1,
                 const float* __restrict__ bih1, const float* __restrict__ bhh1,
                 const float* __restrict__ W1,  const float* __restrict__ b1,
                 const float* __restrict__ W2,  const float* __restrict__ b2,
                 float* __restrict__ out)
{
    extern __shared__ char smraw[];
    const uint32_t raw = smem_u32(smraw);
    const uint32_t BAu = (raw + 1023u) & ~1023u;
    char* BAc = smraw + (BAu - raw);

    const int t    = threadIdx.x;
    const int w    = t >> 5, lane = t & 31;
    const int q    = w;                        // warp owns hidden units 8q..8q+7, ALL gates/batches
    const int g4   = lane >> 2, t4 = lane & 3;
    const int u0   = 8 * q + 2 * t4;           // thread owns units u0, u0+1
    const int bBase = blockIdx.x * BT;

    // ldmatrix lane-invariant address parts
    const int      rlA  = (lane & 7) + ((lane >> 3) & 1) * 8;
    const uint32_t hbA  = (uint32_t)(((lane >> 4) & 1) * 16);
    const uint32_t xorA = (uint32_t)((lane & 7) << 4);
    const int      laneB = lane & 15;
    const int      rlB  = laneB & 7;
    const uint32_t hbB  = (uint32_t)(((laneB >> 3) & 1) * 16);
    const uint32_t xorB = (uint32_t)((laneB & 7) << 4);

    uint32_t aRow[2], bRowW[4];
    #pragma unroll
    for (int mb = 0; mb < 2; mb++) aRow[mb] = (uint32_t)((mb * 16 + rlA) * 128);
    #pragma unroll
    for (int G = 0; G < 4; G++) bRowW[G] = (uint32_t)((G * 64 + 8 * q + rlB) * 128);

    // ---- preload weights: fp32 -> fp16 rounded, SW128 [256][64] ----
    for (int e = t; e < 256 * 64; e += THREADS) {
        int j = e >> 6, k = e & 63;
        uint32_t off = ((uint32_t)(j * 128 + k * 2)) ^ ((uint32_t)(j & 7) << 4);
        *(__half*)(BAc + W0F  + off) = __float2half_rn(Whh0[e]);
        *(__half*)(BAc + W1HF + off) = __float2half_rn(Whh1[e]);
        *(__half*)(BAc + W1IF + off) = __float2half_rn(Wih1[e]);
    }
    for (int e = t; e < 4096; e += THREADS) ((uint32_t*)(BAc + H0T(0)))[e] = 0u;  // all 4 h tiles
    for (int e = t; e < 256;  e += THREADS) ((float*)(BAc + SXO(0)))[e] = 0.f;

    const int xb = t >> 2, xq = t & 3;
    const bool xok = (t < 112) && (bBase + xb < BATCH);
    if (xok) ((float*)(BAc + SXO(0)))[xb * 4 + xq] = x[(size_t)(bBase + xb) * TT * 4 + xq];

    // per-thread constants for units u0, u0+1 (all 4 gates)
    float bias0[4][2], bias1[4][2], w0x[2][4][4];
    #pragma unroll
    for (int G = 0; G < 4; G++)
        #pragma unroll
        for (int ui = 0; ui < 2; ui++) {
            int j = G * 64 + u0 + ui;
            bias0[G][ui] = bih0[j] + bhh0[j];
            bias1[G][ui] = bih1[j] + bhh1[j];
            #pragma unroll
            for (int qq = 0; qq < 4; qq++) w0x[ui][G][qq] = Wih0[j * 4 + qq];
        }
    float c0s[2][2][2], c1s[2][2][2];   // [mb][row-half][ui]
    #pragma unroll
    for (int i = 0; i < 2; i++)
        #pragma unroll
        for (int jj = 0; jj < 2; jj++)
            #pragma unroll
            for (int kk = 0; kk < 2; kk++) { c0s[i][jj][kk] = 0.f; c1s[i][jj][kk] = 0.f; }

    __syncthreads();   // weights + zeroed state visible

    // register-resident Whh0 B-fragments (loop-invariant): [kc][G][2]
    uint32_t bw0[4][4][2];
    #pragma unroll
    for (int kc = 0; kc < 4; kc++)
        #pragma unroll
        for (int G = 0; G < 4; G++)
            ldsm2(bw0[kc][G][0], bw0[kc][G][1],
                  BAu + W0F + bRowW[G] + (((uint32_t)(kc * 32) + hbB) ^ xorB));

    // Wavefront: iter ts computes h0[ts] (ts<TT) and h1[ts-1] (ts>0).
    #pragma unroll 1
    for (int ts = 0; ts <= TT; ts++) {
        const int p = ts & 1;
        float xpre = 0.f;
        if (xok && ts + 1 < TT)
            xpre = x[((size_t)(bBase + xb) * TT + ts + 1) * 4 + xq];

        // ===== layer 1 (step ts-1): acc1 = h1[ts-2]*Whh1^T + h0[ts-1]*Wih1^T =====
        if (ts > 0) {
            float acc1[2][4][4];
            #pragma unroll
            for (int mb = 0; mb < 2; mb++)
                #pragma unroll
                for (int G = 0; G < 4; G++)
                    #pragma unroll
                    for (int c = 0; c < 4; c++) acc1[mb][G][c] = 0.f;
            gemm_hw(acc1, BAu + H1T(p), BAu + W1HF, aRow, bRowW, hbA, xorA, hbB, xorB);
            gemm_hw(acc1, BAu + H0T(p), BAu + W1IF, aRow, bRowW, hbA, xorA, hbB, xorB);

            #pragma unroll
            for (int mb = 0; mb < 2; mb++)
                #pragma unroll
                for (int rh = 0; rh < 2; rh++) {
                    const int b = mb * 16 + g4 + 8 * rh;
                    float hv[2];
                    #pragma unroll
                    for (int ui = 0; ui < 2; ui++) {
                        float pre[4];
                        #pragma unroll
                        for (int G = 0; G < 4; G++)
                            pre[G] = acc1[mb][G][rh * 2 + ui] + bias1[G][ui];
                        float gi = fsig(pre[0]), gf = fsig(pre[1]);
                        float gg = tanhapx(pre[2]), go = fsig(pre[3]);
                        float &c = c1s[mb][rh][ui];
                        c = gf * c + gi * gg;
                        hv[ui] = go * tanhapx(c);
                    }
                    if (ts < TT) {
                        uint32_t off = ((uint32_t)(b * 128 + u0 * 2)) ^ ((uint32_t)(b & 7) << 4);
                        *(__half2*)(BAc + H1T(p ^ 1) + off) =
                            __halves2half2(__float2half_rn(hv[0]), __float2half_rn(hv[1]));
                    } else {
                        *(float2*)((float*)(BAc + HS_OFF) + b * 64 + u0) =
                            make_float2(hv[0], hv[1]);
                    }
                }
        }

        // ===== layer 0 (step ts): acc0 = h0[ts-1]*Whh0^T (resident B); + Wih0*x scalar =====
        if (ts < TT) {
            float acc0[2][4][4];
            #pragma unroll
            for (int mb = 0; mb < 2; mb++)
                #pragma unroll
                for (int G = 0; G < 4; G++)
                    #pragma unroll
                    for (int c = 0; c < 4; c++) acc0[mb][G][c] = 0.f;
            gemm_hres(acc0, BAu + H0T(p), bw0, aRow, hbA, xorA);

            #pragma unroll
            for (int mb = 0; mb < 2; mb++)
                #pragma unroll
                for (int rh = 0; rh < 2; rh++) {
                    const int b = mb * 16 + g4 + 8 * rh;
                    const float4 xv = *(const float4*)(BAc + SXO(p) + b * 16);
                    float hv[2];
                    #pragma unroll
                    for (int ui = 0; ui < 2; ui++) {
                        float pre[4];
                        #pragma unroll
                        for (int G = 0; G < 4; G++)
                            pre[G] = acc0[mb][G][rh * 2 + ui] + bias0[G][ui]
                                   + w0x[ui][G][0] * xv.x + w0x[ui][G][1] * xv.y
                                   + w0x[ui][G][2] * xv.z + w0x[ui][G][3] * xv.w;
                        float gi = fsig(pre[0]), gf = fsig(pre[1]);
                        float gg = tanhapx(pre[2]), go = fsig(pre[3]);
                        float &c = c0s[mb][rh][ui];
                        c = gf * c + gi * gg;
                        hv[ui] = go * tanhapx(c);
                    }
                    uint32_t off = ((uint32_t)(b * 128 + u0 * 2)) ^ ((uint32_t)(b & 7) << 4);
                    *(__half2*)(BAc + H0T(p ^ 1) + off) =
                        __halves2half2(__float2half_rn(hv[0]), __float2half_rn(hv[1]));
                }
            if (t < 112) ((float*)(BAc + SXO(p ^ 1)))[xb * 4 + xq] = xpre;
        }

        __syncthreads();   // single barrier per iteration
    }

    // ================= MLP head =================
    const float* hs = (const float*)(BAc + HS_OFF);   // fp32 h1 final [32][64]
    float* W1s = (float*)(BAc + W1HF);                // W1^T in dead weight region
    for (int e = t; e < 64 * 64; e += THREADS) {
        int n = e >> 6, k = e & 63;
        W1s[k * 64 + n] = W1[e];
    }
    __syncthreads();

    const int u2 = t & 63, pid = t >> 6;
    float bb = b1[u2];
    float zv[7];
    #pragma unroll
    for (int b = 0; b < 7; b++) {
        int row = pid * 7 + b;
        float sum = bb;
        #pragma unroll 8
        for (int k = 0; k < 64; k++)
            sum += W1s[k * 64 + u2] * hs[row * 64 + k];
        zv[b] = fmaxf(sum, 0.f);
    }
    __syncthreads();
    float* sZ = (float*)(BAc + W0F);                  // dead region, [28][64] fp32
    #pragma unroll
    for (int b = 0; b < 7; b++) sZ[(pid * 7 + b) * 64 + u2] = zv[b];
    __syncthreads();

    for (int e = t; e < BT * 12; e += THREADS) {
        int b = e / 12, o = e % 12;
        if (bBase + b < BATCH) {
            float sum = __ldg(&b2[o]);
            #pragma unroll 8
            for (int n = 0; n < 64; n++)
                sum += __ldg(&W2[o * 64 + n]) * sZ[b * 64 + n];
            out[(size_t)(bBase + b) * 12 + o] = sum;
        }
    }
}

extern "C" void kernel_launch(void* const* d_in, const int* in_sizes, int n_in,
                              void* d_out, int out_size)
{
    (void)in_sizes; (void)n_in; (void)out_size;
    cudaFuncSetAttribute(weather_lstm_mma,
                         cudaFuncAttributeMaxDynamicSharedMemorySize, SMEM_BYTES);
    weather_lstm_mma<<<NGRID, THREADS, SMEM_BYTES>>>(
        (const float*)d_in[0],
        (const float*)d_in[1],  (const float*)d_in[2],
        (const float*)d_in[3],  (const float*)d_in[4],
        (const float*)d_in[5],  (const float*)d_in[6],
        (const float*)d_in[7],  (const float*)d_in[8],
        (const float*)d_in[9],  (const float*)d_in[10],
        (const float*)d_in[11], (const float*)d_in[12],
        (float*)d_out);
}

// round 14
// speedup vs baseline: 4.5873x; 1.0684x over previous
#include <cuda_runtime.h>
#include <cuda_fp16.h>
#include <cstdint>

#define THREADS 256
#define BT      28
#define BATCH   4096
#define TT      168
#define NGRID   147

// smem byte offsets from 1024-aligned base
#define W0F    0u        // Whh0 fp16 [256][128B] SW128
#define W1HF   32768u    // Whh1
#define W1IF   65536u    // Wih1
#define W0XP   98304u    // Wih0 K-padded [256][16 fp16 = 32B] compact, 8KB
#define H0T(p)    (106496u + (p)*4096u)   // h0 tile [32][64] fp16 ping-pong
#define H1T(p)    (114688u + (p)*4096u)   // h1 tile
#define SXF(p)    (122880u + (p)*4096u)   // x fp16 tile [32][64] SW128 (cols 0-3 used)
#define HS_OFF    131072u                 // fp32 h1 staging [32][64]
#define SMEM_BYTES 140288

__device__ __forceinline__ uint32_t smem_u32(const void* p) {
    uint32_t a;
    asm("{ .reg .u64 t; cvta.to.shared.u64 t, %1; cvt.u32.u64 %0, t; }" : "=r"(a) : "l"(p));
    return a;
}
__device__ __forceinline__ float tanhapx(float x) {
    float y; asm("tanh.approx.f32 %0, %1;" : "=f"(y) : "f"(x)); return y;
}
__device__ __forceinline__ float fsig(float x) { return fmaf(0.5f, tanhapx(0.5f * x), 0.5f); }

__device__ __forceinline__ void ldsm4(uint32_t &r0, uint32_t &r1, uint32_t &r2, uint32_t &r3, uint32_t a) {
    asm volatile("ldmatrix.sync.aligned.m8n8.x4.shared.b16 {%0,%1,%2,%3}, [%4];"
                 : "=r"(r0), "=r"(r1), "=r"(r2), "=r"(r3) : "r"(a));
}
__device__ __forceinline__ void ldsm2(uint32_t &r0, uint32_t &r1, uint32_t a) {
    asm volatile("ldmatrix.sync.aligned.m8n8.x2.shared.b16 {%0,%1}, [%2];"
                 : "=r"(r0), "=r"(r1) : "r"(a));
}
__device__ __forceinline__ void mma_f16(float &c0, float &c1, float &c2, float &c3,
                                        uint32_t a0, uint32_t a1, uint32_t a2, uint32_t a3,
                                        uint32_t b0, uint32_t b1) {
    asm volatile("mma.sync.aligned.m16n8k16.row.col.f32.f16.f16.f32 "
                 "{%0,%1,%2,%3}, {%4,%5,%6,%7}, {%8,%9}, {%0,%1,%2,%3};"
                 : "+f"(c0), "+f"(c1), "+f"(c2), "+f"(c3)
                 : "r"(a0), "r"(a1), "r"(a2), "r"(a3), "r"(b0), "r"(b1));
}

// acc[mb][G][jj][4] += h(A) * W(B)^T over K=64; warp covers units 16q..16q+15 (jj tiles)
__device__ __forceinline__ void gemm_t(float acc[2][4][2][4],
                                       uint32_t Ah, uint32_t Bw,
                                       const uint32_t aRow[2], const uint32_t bRow[4][2],
                                       uint32_t hbA, uint32_t xorA,
                                       uint32_t hbB, uint32_t xorB)
{
    #pragma unroll
    for (int kc = 0; kc < 4; kc++) {
        const uint32_t kA = ((uint32_t)(kc * 32) + hbA) ^ xorA;
        const uint32_t kB = ((uint32_t)(kc * 32) + hbB) ^ xorB;
        uint32_t a[2][4], b[4][2][2];
        #pragma unroll
        for (int mb = 0; mb < 2; mb++)
            ldsm4(a[mb][0], a[mb][1], a[mb][2], a[mb][3], Ah + aRow[mb] + kA);
        #pragma unroll
        for (int G = 0; G < 4; G++)
            #pragma unroll
            for (int jj = 0; jj < 2; jj++)
                ldsm2(b[G][jj][0], b[G][jj][1], Bw + bRow[G][jj] + kB);
        #pragma unroll
        for (int mb = 0; mb < 2; mb++)
            #pragma unroll
            for (int G = 0; G < 4; G++)
                #pragma unroll
                for (int jj = 0; jj < 2; jj++)
                    mma_f16(acc[mb][G][jj][0], acc[mb][G][jj][1],
                            acc[mb][G][jj][2], acc[mb][G][jj][3],
                            a[mb][0], a[mb][1], a[mb][2], a[mb][3],
                            b[G][jj][0], b[G][jj][1]);
    }
}

extern "C" __global__ void __launch_bounds__(THREADS, 1)
weather_lstm_ws(const float* __restrict__ x,
                const float* __restrict__ Wih0, const float* __restrict__ Whh0,
                const float* __restrict__ bih0, const float* __restrict__ bhh0,
                const float* __restrict__ Wih1, const float* __restrict__ Whh1,
                const float* __restrict__ bih1, const float* __restrict__ bhh1,
                const float* __restrict__ W1,  const float* __restrict__ b1,
                const float* __restrict__ W2,  const float* __restrict__ b2,
                float* __restrict__ out)
{
    extern __shared__ char smraw[];
    const uint32_t raw = smem_u32(smraw);
    const uint32_t BAu = (raw + 1023u) & ~1023u;
    char* BAc = smraw + (BAu - raw);

    const int t    = threadIdx.x;
    const int w    = t >> 5, lane = t & 31;
    const bool isA = (w < 4);                 // team A: layer 0; team B: layer 1
    const int q    = isA ? w : (w - 4);       // warp owns units 16q..16q+15 (all gates)
    const int g4   = lane >> 2, t4 = lane & 3;
    const int u0t  = 16 * q + 2 * t4;         // unit base for (jj=0); +8jj for jj tiles
    const int bBase = blockIdx.x * BT;

    const int      rlA  = (lane & 7) + ((lane >> 3) & 1) * 8;
    const uint32_t hbA  = (uint32_t)(((lane >> 4) & 1) * 16);
    const uint32_t xorA = (uint32_t)((lane & 7) << 4);
    const int      laneB = lane & 15;
    const int      rlB  = laneB & 7;
    const uint32_t hbB  = (uint32_t)(((laneB >> 3) & 1) * 16);
    const uint32_t xorB = (uint32_t)((laneB & 7) << 4);

    uint32_t aRow[2];
    #pragma unroll
    for (int mb = 0; mb < 2; mb++) aRow[mb] = (uint32_t)((mb * 16 + rlA) * 128);
    uint32_t bRow[4][2];
    #pragma unroll
    for (int G = 0; G < 4; G++)
        #pragma unroll
        for (int jj = 0; jj < 2; jj++)
            bRow[G][jj] = (uint32_t)((G * 64 + 16 * q + 8 * jj + rlB) * 128);

    // ---- preload weights fp16 SW128 [256][64] ----
    for (int e = t; e < 256 * 64; e += THREADS) {
        int j = e >> 6, k = e & 63;
        uint32_t off = ((uint32_t)(j * 128 + k * 2)) ^ ((uint32_t)(j & 7) << 4);
        *(__half*)(BAc + W0F  + off) = __float2half_rn(Whh0[e]);
        *(__half*)(BAc + W1HF + off) = __float2half_rn(Whh1[e]);
        *(__half*)(BAc + W1IF + off) = __float2half_rn(Wih1[e]);
    }
    // zero W0XP + h tiles + x tiles (98304..131072 = 32KB contiguous)
    for (int e = t; e < 8192; e += THREADS) ((uint32_t*)(BAc + W0XP))[e] = 0u;
    __syncthreads();   // zeros visible before partial fills below

    // Wih0 -> compact padded tile [256 rows][16 cols fp16 = 32B], cols 0-3 used
    for (int e = t; e < 256 * 4; e += THREADS) {
        int j = e >> 2, i = e & 3;
        *(__half*)(BAc + W0XP + j * 32 + i * 2) = __float2half_rn(Wih0[e]);
    }
    // x(0) fp16 into SXF(0): threads 0..127, one (batch, input) each
    if (t < 128) {
        int xb = t >> 2, xq = t & 3;
        float v = (bBase + xb < BATCH) ? x[(size_t)(bBase + xb) * TT * 4 + xq] : 0.f;
        uint32_t off = ((uint32_t)(xb * 128 + xq * 2)) ^ ((uint32_t)(xb & 7) << 4);
        *(__half*)(BAc + SXF(0) + off) = __float2half_rn(v);
    }

    // per-thread bias (team-specific) for units u0t+8jj+ui, all 4 gates
    float bias[4][2][2];
    #pragma unroll
    for (int G = 0; G < 4; G++)
        #pragma unroll
        for (int jj = 0; jj < 2; jj++)
            #pragma unroll
            for (int ui = 0; ui < 2; ui++) {
                int j = G * 64 + u0t + 8 * jj + ui;
                bias[G][jj][ui] = isA ? (bih0[j] + bhh0[j]) : (bih1[j] + bhh1[j]);
            }
    float cs[2][2][2][2];   // [mb][jj][rh][ui]
    #pragma unroll
    for (int a0 = 0; a0 < 2; a0++)
        #pragma unroll
        for (int a1 = 0; a1 < 2; a1++)
            #pragma unroll
            for (int a2 = 0; a2 < 2; a2++)
                #pragma unroll
                for (int a3 = 0; a3 < 2; a3++) cs[a0][a1][a2][a3] = 0.f;

    // team A: x-duty mapping (thread t == w*32+lane for w<4)
    const int xb = t >> 2, xq = t & 3;
    const bool xok = isA && (bBase + xb < BATCH);

    __syncthreads();

    // team A: resident Wih0-pad B-frags (kc=0 only): [G][jj][2]
    uint32_t bwx[4][2][2];
    if (isA) {
        #pragma unroll
        for (int G = 0; G < 4; G++)
            #pragma unroll
            for (int jj = 0; jj < 2; jj++) {
                uint32_t addr = BAu + W0XP
                              + (uint32_t)((G * 64 + 16 * q + 8 * jj + rlB) * 32)
                              + (uint32_t)(((laneB >> 3) & 1) * 16);
                ldsm2(bwx[G][jj][0], bwx[G][jj][1], addr);
            }
    }

    // Wavefront: iter ts — team A computes h0[ts] (ts<TT); team B computes h1[ts-1] (ts>0).
    // Slots at iter start (p=ts&1): H0T(p)=h0[ts-1], H1T(p)=h1[ts-2], SXF(p)=x[ts].
    #pragma unroll 1
    for (int ts = 0; ts <= TT; ts++) {
        const int p = ts & 1;

        if (isA) {
            if (ts < TT) {
                float xpre = 0.f;
                if (xok && ts + 1 < TT)
                    xpre = x[((size_t)(bBase + xb) * TT + ts + 1) * 4 + xq];

                float acc[2][4][2][4];
                #pragma unroll
                for (int mb = 0; mb < 2; mb++)
                    #pragma unroll
                    for (int G = 0; G < 4; G++)
                        #pragma unroll
                        for (int jj = 0; jj < 2; jj++)
                            #pragma unroll
                            for (int c = 0; c < 4; c++)
                                acc[mb][G][jj][c] = bias[G][jj][c & 1];

                // G0 = h0[ts-1] * Whh0^T
                gemm_t(acc, BAu + H0T(p), BAu + W0F, aRow, bRow, hbA, xorA, hbB, xorB);
                // + x[ts] * Wih0^T  (single K=16 chunk, resident B)
                {
                    const uint32_t kA = hbA ^ xorA;
                    uint32_t a[2][4];
                    #pragma unroll
                    for (int mb = 0; mb < 2; mb++)
                        ldsm4(a[mb][0], a[mb][1], a[mb][2], a[mb][3],
                              BAu + SXF(p) + aRow[mb] + kA);
                    #pragma unroll
                    for (int mb = 0; mb < 2; mb++)
                        #pragma unroll
                        for (int G = 0; G < 4; G++)
                            #pragma unroll
                            for (int jj = 0; jj < 2; jj++)
                                mma_f16(acc[mb][G][jj][0], acc[mb][G][jj][1],
                                        acc[mb][G][jj][2], acc[mb][G][jj][3],
                                        a[mb][0], a[mb][1], a[mb][2], a[mb][3],
                                        bwx[G][jj][0], bwx[G][jj][1]);
                }

                // LSTM cell + store h0[ts] -> H0T(p^1)
                #pragma unroll
                for (int mb = 0; mb < 2; mb++)
                    #pragma unroll
                    for (int jj = 0; jj < 2; jj++)
                        #pragma unroll
                        for (int rh = 0; rh < 2; rh++) {
                            const int b = mb * 16 + g4 + 8 * rh;
                            float hv[2];
                            #pragma unroll
                            for (int ui = 0; ui < 2; ui++) {
                                float gi = fsig   (acc[mb][0][jj][rh * 2 + ui]);
                                float gf = fsig   (acc[mb][1][jj][rh * 2 + ui]);
                                float gg = tanhapx(acc[mb][2][jj][rh * 2 + ui]);
                                float go = fsig   (acc[mb][3][jj][rh * 2 + ui]);
                                float &c = cs[mb][jj][rh][ui];
                                c = gf * c + gi * gg;
                                hv[ui] = go * tanhapx(c);
                            }
                            const int u = u0t + 8 * jj;
                            uint32_t off = ((uint32_t)(b * 128 + u * 2)) ^ ((uint32_t)(b & 7) << 4);
                            *(__half2*)(BAc + H0T(p ^ 1) + off) =
                                __halves2half2(__float2half_rn(hv[0]), __float2half_rn(hv[1]));
                        }

                // stage x[ts+1] -> SXF(p^1)
                {
                    uint32_t off = ((uint32_t)(xb * 128 + xq * 2)) ^ ((uint32_t)(xb & 7) << 4);
                    *(__half*)(BAc + SXF(p ^ 1) + off) = __float2half_rn(xpre);
                }
            }
        } else {
            if (ts > 0) {
                float acc[2][4][2][4];
                #pragma unroll
                for (int mb = 0; mb < 2; mb++)
                    #pragma unroll
                    for (int G = 0; G < 4; G++)
                        #pragma unroll
                        for (int jj = 0; jj < 2; jj++)
                            #pragma unroll
                            for (int c = 0; c < 4; c++)
                                acc[mb][G][jj][c] = bias[G][jj][c & 1];

                // G1 = h1[ts-2]*Whh1^T + h0[ts-1]*Wih1^T
                gemm_t(acc, BAu + H1T(p), BAu + W1HF, aRow, bRow, hbA, xorA, hbB, xorB);
                gemm_t(acc, BAu + H0T(p), BAu + W1IF, aRow, bRow, hbA, xorA, hbB, xorB);

                #pragma unroll
                for (int mb = 0; mb < 2; mb++)
                    #pragma unroll
                    for (int jj = 0; jj < 2; jj++)
                        #pragma unroll
                        for (int rh = 0; rh < 2; rh++) {
                            const int b = mb * 16 + g4 + 8 * rh;
                            float hv[2];
                            #pragma unroll
                            for (int ui = 0; ui < 2; ui++) {
                                float gi = fsig   (acc[mb][0][jj][rh * 2 + ui]);
                                float gf = fsig   (acc[mb][1][jj][rh * 2 + ui]);
                                float gg = tanhapx(acc[mb][2][jj][rh * 2 + ui]);
                                float go = fsig   (acc[mb][3][jj][rh * 2 + ui]);
                                float &c = cs[mb][jj][rh][ui];
                                c = gf * c + gi * gg;
                                hv[ui] = go * tanhapx(c);
                            }
                            const int u = u0t + 8 * jj;
                            if (ts < TT) {
                                uint32_t off = ((uint32_t)(b * 128 + u * 2)) ^ ((uint32_t)(b & 7) << 4);
                                *(__half2*)(BAc + H1T(p ^ 1) + off) =
                                    __halves2half2(__float2half_rn(hv[0]), __float2half_rn(hv[1]));
                            } else {
                                *(float2*)((float*)(BAc + HS_OFF) + b * 64 + u) =
                                    make_float2(hv[0], hv[1]);
                            }
                        }
            }
        }

        __syncthreads();   // single barrier per iteration
    }

    // ================= MLP head =================
    const float* hs = (const float*)(BAc + HS_OFF);   // fp32 h1 final [32][64]
    float* W1s = (float*)(BAc + W1HF);                // W1^T in dead weight region
    for (int e = t; e < 64 * 64; e += THREADS) {
        int n = e >> 6, k = e & 63;
        W1s[k * 64 + n] = W1[e];
    }
    __syncthreads();

    const int u2 = t & 63, pid = t >> 6;
    float bb = b1[u2];
    float zv[7];
    #pragma unroll
    for (int b = 0; b < 7; b++) {
        int row = pid * 7 + b;
        float sum = bb;
        #pragma unroll 8
        for (int k = 0; k < 64; k++)
            sum += W1s[k * 64 + u2] * hs[row * 64 + k];
        zv[b] = fmaxf(sum, 0.f);
    }
    __syncthreads();
    float* sZ = (float*)(BAc + W0F);                  // dead region, [28][64] fp32
    #pragma unroll
    for (int b = 0; b < 7; b++) sZ[(pid * 7 + b) * 64 + u2] = zv[b];
    __syncthreads();

    for (int e = t; e < BT * 12; e += THREADS) {
        int b = e / 12, o = e % 12;
        if (bBase + b < BATCH) {
            float sum = __ldg(&b2[o]);
            #pragma unroll 8
            for (int n = 0; n < 64; n++)
                sum += __ldg(&W2[o * 64 + n]) * sZ[b * 64 + n];
            out[(size_t)(bBase + b) * 12 + o] = sum;
        }
    }
}

extern "C" void kernel_launch(void* const* d_in, const int* in_sizes, int n_in,
                              void* d_out, int out_size)
{
    (void)in_sizes; (void)n_in; (void)out_size;
    cudaFuncSetAttribute(weather_lstm_ws,
                         cudaFuncAttributeMaxDynamicSharedMemorySize, SMEM_BYTES);
    weather_lstm_ws<<<NGRID, THREADS, SMEM_BYTES>>>(
        (const float*)d_in[0],
        (const float*)d_in[1],  (const float*)d_in[2],
        (const float*)d_in[3],  (const float*)d_in[4],
        (const float*)d_in[5],  (const float*)d_in[6],
        (const float*)d_in[7],  (const float*)d_in[8],
        (const float*)d_in[9],  (const float*)d_in[10],
        (const float*)d_in[11], (const float*)d_in[12],
        (float*)d_out);
}

// round 15
// speedup vs baseline: 4.7257x; 1.0302x over previous
#include <cuda_runtime.h>
#include <cuda_fp16.h>
#include <cstdint>

#define THREADS 256
#define BT      28
#define BATCH   4096
#define TT      168
#define NGRID   147

// smem byte offsets from 1024-aligned base
#define W0F    0u        // Whh0 fp16 [256][128B] SW128
#define W1HF   32768u    // Whh1
#define W1IF   65536u    // Wih1
#define W0XP   98304u    // Wih0 K-padded [256][16 fp16 = 32B] compact, 8KB
#define H0T(p)    (106496u + (p)*4096u)   // h0 tile [32][64] fp16 ping-pong
#define H1T(p)    (114688u + (p)*4096u)   // h1 tile
#define SXF(p)    (122880u + (p)*4096u)   // x fp16 tile [32][64] SW128 (cols 0-3 used)
#define HS_OFF    131072u                 // fp32 h1 staging [32][64]
#define SMEM_BYTES 140288

// named barriers: 1 = "h0[ts] ready" (A arrives, B syncs); 2 = "h0 slot free" (B arrives, A syncs)
#define BAR_ARRIVE(id) asm volatile("bar.arrive %0, 256;" :: "r"(id) : "memory")
#define BAR_SYNC(id)   asm volatile("bar.sync %0, 256;"   :: "r"(id) : "memory")

__device__ __forceinline__ uint32_t smem_u32(const void* p) {
    uint32_t a;
    asm("{ .reg .u64 t; cvta.to.shared.u64 t, %1; cvt.u32.u64 %0, t; }" : "=r"(a) : "l"(p));
    return a;
}
__device__ __forceinline__ float tanhapx(float x) {
    float y; asm("tanh.approx.f32 %0, %1;" : "=f"(y) : "f"(x)); return y;
}
__device__ __forceinline__ float fsig(float x) { return fmaf(0.5f, tanhapx(0.5f * x), 0.5f); }

__device__ __forceinline__ void ldsm4(uint32_t &r0, uint32_t &r1, uint32_t &r2, uint32_t &r3, uint32_t a) {
    asm volatile("ldmatrix.sync.aligned.m8n8.x4.shared.b16 {%0,%1,%2,%3}, [%4];"
                 : "=r"(r0), "=r"(r1), "=r"(r2), "=r"(r3) : "r"(a));
}
__device__ __forceinline__ void ldsm2(uint32_t &r0, uint32_t &r1, uint32_t a) {
    asm volatile("ldmatrix.sync.aligned.m8n8.x2.shared.b16 {%0,%1}, [%2];"
                 : "=r"(r0), "=r"(r1) : "r"(a));
}
__device__ __forceinline__ void mma_f16(float &c0, float &c1, float &c2, float &c3,
                                        uint32_t a0, uint32_t a1, uint32_t a2, uint32_t a3,
                                        uint32_t b0, uint32_t b1) {
    asm volatile("mma.sync.aligned.m16n8k16.row.col.f32.f16.f16.f32 "
                 "{%0,%1,%2,%3}, {%4,%5,%6,%7}, {%8,%9}, {%0,%1,%2,%3};"
                 : "+f"(c0), "+f"(c1), "+f"(c2), "+f"(c3)
                 : "r"(a0), "r"(a1), "r"(a2), "r"(a3), "r"(b0), "r"(b1));
}

// acc[mb][G][jj][4] += h(A) * W(B)^T over K=64; warp covers units 16q..16q+15 (jj tiles)
__device__ __forceinline__ void gemm_t(float acc[2][4][2][4],
                                       uint32_t Ah, uint32_t Bw,
                                       const uint32_t aRow[2], const uint32_t bRow[4][2],
                                       uint32_t hbA, uint32_t xorA,
                                       uint32_t hbB, uint32_t xorB)
{
    #pragma unroll
    for (int kc = 0; kc < 4; kc++) {
        const uint32_t kA = ((uint32_t)(kc * 32) + hbA) ^ xorA;
        const uint32_t kB = ((uint32_t)(kc * 32) + hbB) ^ xorB;
        uint32_t a[2][4], b[4][2][2];
        #pragma unroll
        for (int mb = 0; mb < 2; mb++)
            ldsm4(a[mb][0], a[mb][1], a[mb][2], a[mb][3], Ah + aRow[mb] + kA);
        #pragma unroll
        for (int G = 0; G < 4; G++)
            #pragma unroll
            for (int jj = 0; jj < 2; jj++)
                ldsm2(b[G][jj][0], b[G][jj][1], Bw + bRow[G][jj] + kB);
        #pragma unroll
        for (int mb = 0; mb < 2; mb++)
            #pragma unroll
            for (int G = 0; G < 4; G++)
                #pragma unroll
                for (int jj = 0; jj < 2; jj++)
                    mma_f16(acc[mb][G][jj][0], acc[mb][G][jj][1],
                            acc[mb][G][jj][2], acc[mb][G][jj][3],
                            a[mb][0], a[mb][1], a[mb][2], a[mb][3],
                            b[G][jj][0], b[G][jj][1]);
    }
}

extern "C" __global__ void __launch_bounds__(THREADS, 1)
weather_lstm_ws(const float* __restrict__ x,
                const float* __restrict__ Wih0, const float* __restrict__ Whh0,
                const float* __restrict__ bih0, const float* __restrict__ bhh0,
                const float* __restrict__ Wih1, const float* __restrict__ Whh1,
                const float* __restrict__ bih1, const float* __restrict__ bhh1,
                const float* __restrict__ W1,  const float* __restrict__ b1,
                const float* __restrict__ W2,  const float* __restrict__ b2,
                float* __restrict__ out)
{
    extern __shared__ char smraw[];
    const uint32_t raw = smem_u32(smraw);
    const uint32_t BAu = (raw + 1023u) & ~1023u;
    char* BAc = smraw + (BAu - raw);

    const int t    = threadIdx.x;
    const int w    = t >> 5, lane = t & 31;
    const bool isA = (w < 4);                 // team A: layer 0; team B: layer 1
    const int q    = isA ? w : (w - 4);       // warp owns units 16q..16q+15 (all gates)
    const int g4   = lane >> 2, t4 = lane & 3;
    const int u0t  = 16 * q + 2 * t4;
    const int bBase = blockIdx.x * BT;

    const int      rlA  = (lane & 7) + ((lane >> 3) & 1) * 8;
    const uint32_t hbA  = (uint32_t)(((lane >> 4) & 1) * 16);
    const uint32_t xorA = (uint32_t)((lane & 7) << 4);
    const int      laneB = lane & 15;
    const int      rlB  = laneB & 7;
    const uint32_t hbB  = (uint32_t)(((laneB >> 3) & 1) * 16);
    const uint32_t xorB = (uint32_t)((laneB & 7) << 4);

    uint32_t aRow[2];
    #pragma unroll
    for (int mb = 0; mb < 2; mb++) aRow[mb] = (uint32_t)((mb * 16 + rlA) * 128);
    uint32_t bRow[4][2];
    #pragma unroll
    for (int G = 0; G < 4; G++)
        #pragma unroll
        for (int jj = 0; jj < 2; jj++)
            bRow[G][jj] = (uint32_t)((G * 64 + 16 * q + 8 * jj + rlB) * 128);

    // ---- preload weights fp16 SW128 [256][64] ----
    for (int e = t; e < 256 * 64; e += THREADS) {
        int j = e >> 6, k = e & 63;
        uint32_t off = ((uint32_t)(j * 128 + k * 2)) ^ ((uint32_t)(j & 7) << 4);
        *(__half*)(BAc + W0F  + off) = __float2half_rn(Whh0[e]);
        *(__half*)(BAc + W1HF + off) = __float2half_rn(Whh1[e]);
        *(__half*)(BAc + W1IF + off) = __float2half_rn(Wih1[e]);
    }
    for (int e = t; e < 8192; e += THREADS) ((uint32_t*)(BAc + W0XP))[e] = 0u;
    __syncthreads();

    for (int e = t; e < 256 * 4; e += THREADS) {
        int j = e >> 2, i = e & 3;
        *(__half*)(BAc + W0XP + j * 32 + i * 2) = __float2half_rn(Wih0[e]);
    }
    if (t < 128) {
        int xb2 = t >> 2, xq2 = t & 3;
        float v = (bBase + xb2 < BATCH) ? x[(size_t)(bBase + xb2) * TT * 4 + xq2] : 0.f;
        uint32_t off = ((uint32_t)(xb2 * 128 + xq2 * 2)) ^ ((uint32_t)(xb2 & 7) << 4);
        *(__half*)(BAc + SXF(0) + off) = __float2half_rn(v);
    }

    float bias[4][2][2];
    #pragma unroll
    for (int G = 0; G < 4; G++)
        #pragma unroll
        for (int jj = 0; jj < 2; jj++)
            #pragma unroll
            for (int ui = 0; ui < 2; ui++) {
                int j = G * 64 + u0t + 8 * jj + ui;
                bias[G][jj][ui] = isA ? (bih0[j] + bhh0[j]) : (bih1[j] + bhh1[j]);
            }
    float cs[2][2][2][2];
    #pragma unroll
    for (int a0 = 0; a0 < 2; a0++)
        #pragma unroll
        for (int a1 = 0; a1 < 2; a1++)
            #pragma unroll
            for (int a2 = 0; a2 < 2; a2++)
                #pragma unroll
                for (int a3 = 0; a3 < 2; a3++) cs[a0][a1][a2][a3] = 0.f;

    const int xb = t >> 2, xq = t & 3;
    const bool xok = isA && (bBase + xb < BATCH);

    __syncthreads();

    uint32_t bwx[4][2][2];
    if (isA) {
        #pragma unroll
        for (int G = 0; G < 4; G++)
            #pragma unroll
            for (int jj = 0; jj < 2; jj++) {
                uint32_t addr = BAu + W0XP
                              + (uint32_t)((G * 64 + 16 * q + 8 * jj + rlB) * 32)
                              + (uint32_t)(((laneB >> 3) & 1) * 16);
                ldsm2(bwx[G][jj][0], bwx[G][jj][1], addr);
            }
        BAR_ARRIVE(1);   // prime "h0 ready" so B's first sync releases
    }

    // Wavefront with producer/consumer handshake (no CTA-wide barrier in loop).
    #pragma unroll 1
    for (int ts = 0; ts <= TT; ts++) {
        const int p = ts & 1;

        if (isA) {
            if (ts < TT) {
                float xpre = 0.f;
                if (xok && ts + 1 < TT)
                    xpre = x[((size_t)(bBase + xb) * TT + ts + 1) * 4 + xq];

                float acc[2][4][2][4];
                #pragma unroll
                for (int mb = 0; mb < 2; mb++)
                    #pragma unroll
                    for (int G = 0; G < 4; G++)
                        #pragma unroll
                        for (int jj = 0; jj < 2; jj++)
                            #pragma unroll
                            for (int c = 0; c < 4; c++)
                                acc[mb][G][jj][c] = bias[G][jj][c & 1];

                gemm_t(acc, BAu + H0T(p), BAu + W0F, aRow, bRow, hbA, xorA, hbB, xorB);
                {   // + x[ts] * Wih0^T (single K=16 chunk, resident B)
                    const uint32_t kA = hbA ^ xorA;
                    uint32_t a[2][4];
                    #pragma unroll
                    for (int mb = 0; mb < 2; mb++)
                        ldsm4(a[mb][0], a[mb][1], a[mb][2], a[mb][3],
                              BAu + SXF(p) + aRow[mb] + kA);
                    #pragma unroll
                    for (int mb = 0; mb < 2; mb++)
                        #pragma unroll
                        for (int G = 0; G < 4; G++)
                            #pragma unroll
                            for (int jj = 0; jj < 2; jj++)
                                mma_f16(acc[mb][G][jj][0], acc[mb][G][jj][1],
                                        acc[mb][G][jj][2], acc[mb][G][jj][3],
                                        a[mb][0], a[mb][1], a[mb][2], a[mb][3],
                                        bwx[G][jj][0], bwx[G][jj][1]);
                }

                // act into registers (overlaps B's gemm2/act on the other warp)
                __half2 hv2[2][2][2];
                #pragma unroll
                for (int mb = 0; mb < 2; mb++)
                    #pragma unroll
                    for (int jj = 0; jj < 2; jj++)
                        #pragma unroll
                        for (int rh = 0; rh < 2; rh++) {
                            float hv[2];
                            #pragma unroll
                            for (int ui = 0; ui < 2; ui++) {
                                float gi = fsig   (acc[mb][0][jj][rh * 2 + ui]);
                                float gf = fsig   (acc[mb][1][jj][rh * 2 + ui]);
                                float gg = tanhapx(acc[mb][2][jj][rh * 2 + ui]);
                                float go = fsig   (acc[mb][3][jj][rh * 2 + ui]);
                                float &c = cs[mb][jj][rh][ui];
                                c = gf * c + gi * gg;
                                hv[ui] = go * tanhapx(c);
                            }
                            hv2[mb][jj][rh] = __halves2half2(__float2half_rn(hv[0]),
                                                             __float2half_rn(hv[1]));
                        }

                BAR_SYNC(2);   // wait: B finished reading H0T(p^1) (its iter ts-1)
                #pragma unroll
                for (int mb = 0; mb < 2; mb++)
                    #pragma unroll
                    for (int jj = 0; jj < 2; jj++)
                        #pragma unroll
                        for (int rh = 0; rh < 2; rh++) {
                            const int b = mb * 16 + g4 + 8 * rh;
                            const int u = u0t + 8 * jj;
                            uint32_t off = ((uint32_t)(b * 128 + u * 2)) ^ ((uint32_t)(b & 7) << 4);
                            *(__half2*)(BAc + H0T(p ^ 1) + off) = hv2[mb][jj][rh];
                        }
                {
                    uint32_t off = ((uint32_t)(xb * 128 + xq * 2)) ^ ((uint32_t)(xb & 7) << 4);
                    *(__half*)(BAc + SXF(p ^ 1) + off) = __float2half_rn(xpre);
                }
                BAR_ARRIVE(1); // h0[ts] ready
            } else {
                BAR_SYNC(2); BAR_ARRIVE(1);
            }
        } else {
            if (ts > 0) {
                float acc[2][4][2][4];
                #pragma unroll
                for (int mb = 0; mb < 2; mb++)
                    #pragma unroll
                    for (int G = 0; G < 4; G++)
                        #pragma unroll
                        for (int jj = 0; jj < 2; jj++)
                            #pragma unroll
                            for (int c = 0; c < 4; c++)
                                acc[mb][G][jj][c] = bias[G][jj][c & 1];

                // own-layer term first (no cross-team wait)
                gemm_t(acc, BAu + H1T(p), BAu + W1HF, aRow, bRow, hbA, xorA, hbB, xorB);
                BAR_SYNC(1);   // h0[ts-1] ready (A iter ts-1 arrived)
                gemm_t(acc, BAu + H0T(p), BAu + W1IF, aRow, bRow, hbA, xorA, hbB, xorB);
                BAR_ARRIVE(2); // done reading H0T(p) — A may overwrite

                #pragma unroll
                for (int mb = 0; mb < 2; mb++)
                    #pragma unroll
                    for (int jj = 0; jj < 2; jj++)
                        #pragma unroll
                        for (int rh = 0; rh < 2; rh++) {
                            const int b = mb * 16 + g4 + 8 * rh;
                            float hv[2];
                            #pragma unroll
                            for (int ui = 0; ui < 2; ui++) {
                                float gi = fsig   (acc[mb][0][jj][rh * 2 + ui]);
                                float gf = fsig   (acc[mb][1][jj][rh * 2 + ui]);
                                float gg = tanhapx(acc[mb][2][jj][rh * 2 + ui]);
                                float go = fsig   (acc[mb][3][jj][rh * 2 + ui]);
                                float &c = cs[mb][jj][rh][ui];
                                c = gf * c + gi * gg;
                                hv[ui] = go * tanhapx(c);
                            }
                            const int u = u0t + 8 * jj;
                            if (ts < TT) {
                                uint32_t off = ((uint32_t)(b * 128 + u * 2)) ^ ((uint32_t)(b & 7) << 4);
                                *(__half2*)(BAc + H1T(p ^ 1) + off) =
                                    __halves2half2(__float2half_rn(hv[0]), __float2half_rn(hv[1]));
                            } else {
                                *(float2*)((float*)(BAc + HS_OFF) + b * 64 + u) =
                                    make_float2(hv[0], hv[1]);
                            }
                        }
            } else {
                BAR_SYNC(1); BAR_ARRIVE(2);
            }
        }
    }

    __syncthreads();   // rejoin before reusing weight regions

    // ================= MLP head =================
    const float* hs = (const float*)(BAc + HS_OFF);
    float* W1s = (float*)(BAc + W1HF);
    for (int e = t; e < 64 * 64; e += THREADS) {
        int n = e >> 6, k = e & 63;
        W1s[k * 64 + n] = W1[e];
    }
    __syncthreads();

    const int u2 = t & 63, pid = t >> 6;
    float bb = b1[u2];
    float zv[7];
    #pragma unroll
    for (int b = 0; b < 7; b++) {
        int row = pid * 7 + b;
        float sum = bb;
        #pragma unroll 8
        for (int k = 0; k < 64; k++)
            sum += W1s[k * 64 + u2] * hs[row * 64 + k];
        zv[b] = fmaxf(sum, 0.f);
    }
    __syncthreads();
    float* sZ = (float*)(BAc + W0F);
    #pragma unroll
    for (int b = 0; b < 7; b++) sZ[(pid * 7 + b) * 64 + u2] = zv[b];
    __syncthreads();

    for (int e = t; e < BT * 12; e += THREADS) {
        int b = e / 12, o = e % 12;
        if (bBase + b < BATCH) {
            float sum = __ldg(&b2[o]);
            #pragma unroll 8
            for (int n = 0; n < 64; n++)
                sum += __ldg(&W2[o * 64 + n]) * sZ[b * 64 + n];
            out[(size_t)(bBase + b) * 12 + o] = sum;
        }
    }
}

extern "C" void kernel_launch(void* const* d_in, const int* in_sizes, int n_in,
                              void* d_out, int out_size)
{
    (void)in_sizes; (void)n_in; (void)out_size;
    cudaFuncSetAttribute(weather_lstm_ws,
                         cudaFuncAttributeMaxDynamicSharedMemorySize, SMEM_BYTES);
    weather_lstm_ws<<<NGRID, THREADS, SMEM_BYTES>>>(
        (const float*)d_in[0],
        (const float*)d_in[1],  (const float*)d_in[2],
        (const float*)d_in[3],  (const float*)d_in[4],
        (const float*)d_in[5],  (const float*)d_in[6],
        (const float*)d_in[7],  (const float*)d_in[8],
        (const float*)d_in[9],  (const float*)d_in[10],
        (const float*)d_in[11], (const float*)d_in[12],
        (float*)d_out);
}